// round 2
// baseline (speedup 1.0000x reference)
#include <cuda_runtime.h>
#include <cstdint>

// Problem constants
#define BSZ 2
#define SEQ 2048
#define DM 1024
#define NH 16
#define HD 64
#define MROWS (BSZ * SEQ)     // 4096
#define QKV_N (3 * DM)        // 3072

// Scratch (allocation-free rule: __device__ globals)
__device__ float g_qkv[MROWS * QKV_N];   // [4096, 3072]
__device__ float g_attn[MROWS * DM];     // [4096, 1024]

// ---------------------------------------------------------------------------
// SGEMM: C[M,N] = A[M,K] @ B[K,N] + bias[N]   (row-major, all dims % tile == 0)
// 128x128 block tile, BK=16, 256 threads, 8x8 micro-tile per thread.
// If C == nullptr, writes to g_qkv (avoids host-side symbol lookups).
// ---------------------------------------------------------------------------
__global__ __launch_bounds__(256) void sgemm128(
    const float* __restrict__ A, const float* __restrict__ B,
    const float* __restrict__ bias, float* __restrict__ C,
    int M, int N, int K)
{
    __shared__ float As[16][129];   // transposed: As[k][m], padded
    __shared__ float Bs[16][128];   // Bs[k][n]

    if (C == nullptr) C = g_qkv;

    const int tid = threadIdx.x;
    const int block_row = blockIdx.y * 128;
    const int block_col = blockIdx.x * 128;

    // A load indices: 128 rows x 16 cols, float4 along K. 512 float4 / 256 thr = 2
    const int a_row = tid >> 2;            // 0..63
    const int a_col = (tid & 3) * 4;       // 0,4,8,12
    // B load indices: 16 rows x 128 cols. 512 float4 / 256 thr = 2
    const int b_row = tid >> 5;            // 0..7
    const int b_col = (tid & 31) * 4;

    const int ty = tid >> 4;               // 0..15
    const int tx = tid & 15;               // 0..15

    float acc[8][8];
#pragma unroll
    for (int i = 0; i < 8; i++)
#pragma unroll
        for (int j = 0; j < 8; j++) acc[i][j] = 0.0f;

    for (int k0 = 0; k0 < K; k0 += 16) {
        float4 a0 = *(const float4*)&A[(size_t)(block_row + a_row) * K + k0 + a_col];
        float4 a1 = *(const float4*)&A[(size_t)(block_row + a_row + 64) * K + k0 + a_col];
        As[a_col + 0][a_row] = a0.x;
        As[a_col + 1][a_row] = a0.y;
        As[a_col + 2][a_row] = a0.z;
        As[a_col + 3][a_row] = a0.w;
        As[a_col + 0][a_row + 64] = a1.x;
        As[a_col + 1][a_row + 64] = a1.y;
        As[a_col + 2][a_row + 64] = a1.z;
        As[a_col + 3][a_row + 64] = a1.w;

        float4 b0 = *(const float4*)&B[(size_t)(k0 + b_row) * N + block_col + b_col];
        float4 b1 = *(const float4*)&B[(size_t)(k0 + b_row + 8) * N + block_col + b_col];
        *(float4*)&Bs[b_row][b_col] = b0;
        *(float4*)&Bs[b_row + 8][b_col] = b1;

        __syncthreads();

#pragma unroll
        for (int kk = 0; kk < 16; kk++) {
            float af[8], bf[8];
#pragma unroll
            for (int i = 0; i < 8; i++) af[i] = As[kk][ty * 8 + i];
#pragma unroll
            for (int j = 0; j < 8; j++) bf[j] = Bs[kk][tx * 8 + j];
#pragma unroll
            for (int i = 0; i < 8; i++)
#pragma unroll
                for (int j = 0; j < 8; j++) acc[i][j] = fmaf(af[i], bf[j], acc[i][j]);
        }
        __syncthreads();
    }

#pragma unroll
    for (int i = 0; i < 8; i++) {
        const int row = block_row + ty * 8 + i;
#pragma unroll
        for (int j = 0; j < 8; j += 4) {
            const int col = block_col + tx * 8 + j;
            float4 r;
            r.x = acc[i][j + 0] + bias[col + 0];
            r.y = acc[i][j + 1] + bias[col + 1];
            r.z = acc[i][j + 2] + bias[col + 2];
            r.w = acc[i][j + 3] + bias[col + 3];
            *(float4*)&C[(size_t)row * N + col] = r;
        }
    }
}

// ---------------------------------------------------------------------------
// Flash attention (fp32, causal). One CTA = (batch b, head h, 64-row Q tile).
// Reads g_qkv directly: q at col h*64, k at DM + h*64, v at 2*DM + h*64.
// Writes g_attn [b*SEQ + l, DM] at col h*64 (out-proj GEMM reads it directly).
// 128 threads: tr = tid/8 in [0,16) -> 4 query rows each; tc = tid%8 -> 8 cols.
// smem: Qs,Ks,Vs,Ps each 64x65 fp32 (padded) = 66,560 B dynamic.
// ---------------------------------------------------------------------------
#define ATTN_SMEM (4 * 64 * 65 * 4)

__global__ __launch_bounds__(128) void flash_attn_kernel()
{
    extern __shared__ float smem[];
    float* Qs = smem;               // [64][65]
    float* Ks = Qs + 64 * 65;
    float* Vs = Ks + 64 * 65;
    float* Ps = Vs + 64 * 65;

    const float* qkv = g_qkv;

    const int qt = blockIdx.x;      // query tile 0..31
    const int h  = blockIdx.y;
    const int b  = blockIdx.z;
    const int tid = threadIdx.x;
    const int tr = tid >> 3;        // 0..15
    const int tc = tid & 7;         // 0..7

    const size_t row0 = (size_t)b * SEQ + qt * 64;
    const float* qbase = qkv + row0 * QKV_N + h * HD;

    // Load Q tile: 64 rows x 16 float4 = 1024 units / 128 thr = 8 each
    for (int u = tid; u < 64 * 16; u += 128) {
        const int r = u >> 4;
        const int c4 = (u & 15) * 4;
        float4 v = *(const float4*)&qbase[(size_t)r * QKV_N + c4];
        float* dst = &Qs[r * 65 + c4];
        dst[0] = v.x; dst[1] = v.y; dst[2] = v.z; dst[3] = v.w;
    }

    float m_i[4], l_i[4], acc[4][8];
#pragma unroll
    for (int i = 0; i < 4; i++) {
        m_i[i] = -1e30f; l_i[i] = 0.0f;
#pragma unroll
        for (int d = 0; d < 8; d++) acc[i][d] = 0.0f;
    }

    const float scale = 0.03125f;   // 1/sqrt(1024)

    for (int kt = 0; kt <= qt; kt++) {
        // Load K and V tiles (rows kt*64 .. +63)
        const size_t krow0 = (size_t)b * SEQ + kt * 64;
        const float* kbase = qkv + krow0 * QKV_N + DM + h * HD;
        const float* vbase = qkv + krow0 * QKV_N + 2 * DM + h * HD;
        for (int u = tid; u < 64 * 16; u += 128) {
            const int r = u >> 4;
            const int c4 = (u & 15) * 4;
            float4 kv = *(const float4*)&kbase[(size_t)r * QKV_N + c4];
            float* kd = &Ks[r * 65 + c4];
            kd[0] = kv.x; kd[1] = kv.y; kd[2] = kv.z; kd[3] = kv.w;
            float4 vv = *(const float4*)&vbase[(size_t)r * QKV_N + c4];
            float* vd = &Vs[r * 65 + c4];
            vd[0] = vv.x; vd[1] = vv.y; vd[2] = vv.z; vd[3] = vv.w;
        }
        __syncthreads();

        // S = Q K^T for this thread's 4x8 block
        float s[4][8];
#pragma unroll
        for (int i = 0; i < 4; i++)
#pragma unroll
            for (int j = 0; j < 8; j++) s[i][j] = 0.0f;

        for (int d = 0; d < 64; d++) {
            float qv[4], kv[8];
#pragma unroll
            for (int i = 0; i < 4; i++) qv[i] = Qs[(tr * 4 + i) * 65 + d];
#pragma unroll
            for (int j = 0; j < 8; j++) kv[j] = Ks[(tc * 8 + j) * 65 + d];
#pragma unroll
            for (int i = 0; i < 4; i++)
#pragma unroll
                for (int j = 0; j < 8; j++) s[i][j] = fmaf(qv[i], kv[j], s[i][j]);
        }

        const bool diag = (kt == qt);
#pragma unroll
        for (int i = 0; i < 4; i++) {
            const int qi = tr * 4 + i;
#pragma unroll
            for (int j = 0; j < 8; j++) {
                const int kj = tc * 8 + j;
                s[i][j] *= scale;
                if (diag && kj > qi) s[i][j] = -1e30f;
            }
        }

        // Online softmax per row (reduce across the 8 lanes of the row group)
#pragma unroll
        for (int i = 0; i < 4; i++) {
            float mt = s[i][0];
#pragma unroll
            for (int j = 1; j < 8; j++) mt = fmaxf(mt, s[i][j]);
            mt = fmaxf(mt, __shfl_xor_sync(0xffffffffu, mt, 1));
            mt = fmaxf(mt, __shfl_xor_sync(0xffffffffu, mt, 2));
            mt = fmaxf(mt, __shfl_xor_sync(0xffffffffu, mt, 4));

            const float m_new = fmaxf(m_i[i], mt);
            const float alpha = __expf(m_i[i] - m_new);
            float ls = 0.0f;
#pragma unroll
            for (int j = 0; j < 8; j++) {
                const float p = __expf(s[i][j] - m_new);
                s[i][j] = p;
                ls += p;
            }
            ls += __shfl_xor_sync(0xffffffffu, ls, 1);
            ls += __shfl_xor_sync(0xffffffffu, ls, 2);
            ls += __shfl_xor_sync(0xffffffffu, ls, 4);

            l_i[i] = l_i[i] * alpha + ls;
            m_i[i] = m_new;
#pragma unroll
            for (int d = 0; d < 8; d++) acc[i][d] *= alpha;
#pragma unroll
            for (int j = 0; j < 8; j++)
                Ps[(tr * 4 + i) * 65 + tc * 8 + j] = s[i][j];
        }
        __syncthreads();

        // O += P @ V
        for (int j = 0; j < 64; j++) {
            float pv[4], vv[8];
#pragma unroll
            for (int i = 0; i < 4; i++) pv[i] = Ps[(tr * 4 + i) * 65 + j];
#pragma unroll
            for (int d = 0; d < 8; d++) vv[d] = Vs[j * 65 + tc * 8 + d];
#pragma unroll
            for (int i = 0; i < 4; i++)
#pragma unroll
                for (int d = 0; d < 8; d++) acc[i][d] = fmaf(pv[i], vv[d], acc[i][d]);
        }
        __syncthreads();
    }

    // Normalize and write to the attention scratch in [row, DM] layout
#pragma unroll
    for (int i = 0; i < 4; i++) {
        const float inv = 1.0f / l_i[i];
        const size_t row = row0 + tr * 4 + i;
        float* dst = &g_attn[row * DM + h * HD + tc * 8];
        float4 r0, r1;
        r0.x = acc[i][0] * inv; r0.y = acc[i][1] * inv;
        r0.z = acc[i][2] * inv; r0.w = acc[i][3] * inv;
        r1.x = acc[i][4] * inv; r1.y = acc[i][5] * inv;
        r1.z = acc[i][6] * inv; r1.w = acc[i][7] * inv;
        *(float4*)&dst[0] = r0;
        *(float4*)&dst[4] = r1;
    }
}

// ---------------------------------------------------------------------------
// Launcher
// ---------------------------------------------------------------------------
extern "C" void kernel_launch(void* const* d_in, const int* in_sizes, int n_in,
                              void* d_out, int out_size)
{
    const float* x     = (const float*)d_in[0];
    const float* w_qkv = (const float*)d_in[1];
    const float* b_qkv = (const float*)d_in[2];
    const float* w_out = (const float*)d_in[3];
    const float* b_out = (const float*)d_in[4];
    float* out = (float*)d_out;

    float* attn_ptr = nullptr;
    cudaGetSymbolAddress((void**)&attn_ptr, g_attn);

    cudaFuncSetAttribute(flash_attn_kernel,
                         cudaFuncAttributeMaxDynamicSharedMemorySize, ATTN_SMEM);

    // 1) QKV = x @ w_qkv + b_qkv   [4096, 3072]  (C=nullptr -> writes g_qkv)
    sgemm128<<<dim3(QKV_N / 128, MROWS / 128), 256>>>(
        x, w_qkv, b_qkv, nullptr, MROWS, QKV_N, DM);

    // 2) Attention: g_qkv -> g_attn [4096, 1024]
    flash_attn_kernel<<<dim3(SEQ / 64, NH, BSZ), 128, ATTN_SMEM>>>();

    // 3) out = attn @ w_out + b_out   [4096, 1024]
    sgemm128<<<dim3(DM / 128, MROWS / 128), 256>>>(
        attn_ptr, w_out, b_out, out, MROWS, DM, DM);
}

// round 4
// speedup vs baseline: 1.3533x; 1.3533x over previous
#include <cuda_runtime.h>
#include <cuda_bf16.h>
#include <cstdint>

// Problem constants
#define BSZ 2
#define SEQ 2048
#define DM 1024
#define NH 16
#define HD 64
#define MROWS 4096
#define QKV_N 3072
#define KDIM 1024

// ---------------------------------------------------------------------------
// Scratch (__device__ globals; allocation-free rule)
// ---------------------------------------------------------------------------
__device__ float g_qkv[MROWS * QKV_N];    // [4096, 3072] fp32
__device__ float g_attn[MROWS * DM];      // [4096, 1024] fp32
__device__ __align__(16) __nv_bfloat16 g_x_hi[MROWS * KDIM];
__device__ __align__(16) __nv_bfloat16 g_x_lo[MROWS * KDIM];
__device__ __align__(16) __nv_bfloat16 g_wq_hi[QKV_N * KDIM];  // w_qkv^T [3072,1024]
__device__ __align__(16) __nv_bfloat16 g_wq_lo[QKV_N * KDIM];
__device__ __align__(16) __nv_bfloat16 g_wo_hi[DM * KDIM];     // w_out^T [1024,1024]
__device__ __align__(16) __nv_bfloat16 g_wo_lo[DM * KDIM];
__device__ __align__(16) __nv_bfloat16 g_at_hi[MROWS * KDIM];
__device__ __align__(16) __nv_bfloat16 g_at_lo[MROWS * KDIM];

// ---------------------------------------------------------------------------
// mma.sync / ldmatrix helpers (sm_80-compatible: compiles under compute_100)
// ---------------------------------------------------------------------------
__device__ __forceinline__ uint32_t smem_u32(const void* p) {
    uint32_t a;
    asm("{ .reg .u64 t; cvta.to.shared.u64 t, %1; cvt.u32.u64 %0, t; }" : "=r"(a) : "l"(p));
    return a;
}

__device__ __forceinline__ void ldmx4(uint32_t& r0, uint32_t& r1, uint32_t& r2,
                                      uint32_t& r3, uint32_t addr) {
    asm volatile("ldmatrix.sync.aligned.m8n8.x4.shared.b16 {%0,%1,%2,%3}, [%4];"
                 : "=r"(r0), "=r"(r1), "=r"(r2), "=r"(r3) : "r"(addr));
}
__device__ __forceinline__ void ldmx2(uint32_t& r0, uint32_t& r1, uint32_t addr) {
    asm volatile("ldmatrix.sync.aligned.m8n8.x2.shared.b16 {%0,%1}, [%2];"
                 : "=r"(r0), "=r"(r1) : "r"(addr));
}

__device__ __forceinline__ void mma_bf16(float* c, const uint32_t* a, const uint32_t* b) {
    asm volatile(
        "mma.sync.aligned.m16n8k16.row.col.f32.bf16.bf16.f32 "
        "{%0,%1,%2,%3}, {%4,%5,%6,%7}, {%8,%9}, {%0,%1,%2,%3};"
        : "+f"(c[0]), "+f"(c[1]), "+f"(c[2]), "+f"(c[3])
        : "r"(a[0]), "r"(a[1]), "r"(a[2]), "r"(a[3]), "r"(b[0]), "r"(b[1]));
}

// ---------------------------------------------------------------------------
// Split fp32 -> bf16 hi/lo (same layout), vectorized x4
// ---------------------------------------------------------------------------
__device__ __forceinline__ uint32_t pack2bf(__nv_bfloat16 a, __nv_bfloat16 b) {
    __nv_bfloat162 t = __halves2bfloat162(a, b);
    return *reinterpret_cast<uint32_t*>(&t);
}

__global__ __launch_bounds__(256) void split_f32(
    const float* __restrict__ src, __nv_bfloat16* __restrict__ hi,
    __nv_bfloat16* __restrict__ lo, int n)
{
    int i = (blockIdx.x * 256 + threadIdx.x) * 4;
    if (i >= n) return;
    float4 v = *(const float4*)&src[i];
    __nv_bfloat16 h0 = __float2bfloat16(v.x);
    __nv_bfloat16 h1 = __float2bfloat16(v.y);
    __nv_bfloat16 h2 = __float2bfloat16(v.z);
    __nv_bfloat16 h3 = __float2bfloat16(v.w);
    __nv_bfloat16 l0 = __float2bfloat16(v.x - __bfloat162float(h0));
    __nv_bfloat16 l1 = __float2bfloat16(v.y - __bfloat162float(h1));
    __nv_bfloat16 l2 = __float2bfloat16(v.z - __bfloat162float(h2));
    __nv_bfloat16 l3 = __float2bfloat16(v.w - __bfloat162float(h3));
    *(uint2*)&hi[i] = make_uint2(pack2bf(h0, h1), pack2bf(h2, h3));
    *(uint2*)&lo[i] = make_uint2(pack2bf(l0, l1), pack2bf(l2, l3));
}

// ---------------------------------------------------------------------------
// Transpose + split: w [K, N] fp32 row-major -> th/tl [N, K] bf16
// ---------------------------------------------------------------------------
__global__ __launch_bounds__(256) void transpose_split(
    const float* __restrict__ w, __nv_bfloat16* __restrict__ th,
    __nv_bfloat16* __restrict__ tl, int K, int N)
{
    __shared__ float tile[32][33];
    const int nx = blockIdx.x * 32 + threadIdx.x;   // N index (read)
    const int k0 = blockIdx.y * 32;
#pragma unroll
    for (int j = 0; j < 32; j += 8)
        tile[threadIdx.y + j][threadIdx.x] = w[(size_t)(k0 + threadIdx.y + j) * N + nx];
    __syncthreads();
    const int kx = k0 + threadIdx.x;                // K index (write)
    const int n0 = blockIdx.x * 32;
#pragma unroll
    for (int j = 0; j < 32; j += 8) {
        float v = tile[threadIdx.x][threadIdx.y + j];
        __nv_bfloat16 h = __float2bfloat16(v);
        th[(size_t)(n0 + threadIdx.y + j) * K + kx] = h;
        tl[(size_t)(n0 + threadIdx.y + j) * K + kx] = __float2bfloat16(v - __bfloat162float(h));
    }
}

// ---------------------------------------------------------------------------
// Split-bf16 mma.sync GEMM: C[M,N] = (Ah+Al)[M,K] @ (Bh+Bl)[N,K]^T + bias
// A row-major [M,K] (K-major), B row-major [N,K] (K-major). K = 1024 fixed.
// CTA tile 128x128, BK=32, 256 threads = 8 warps (2 x 4), warp tile 64x32.
// 3 split terms: AhBh + AhBl + AlBh; fp32 register accumulators.
// ---------------------------------------------------------------------------
#define BKP 40   // padded row length in bf16 elems (80 B rows: conflict-free ldmatrix)

__global__ __launch_bounds__(256) void gemm_mma(
    const __nv_bfloat16* __restrict__ Ah, const __nv_bfloat16* __restrict__ Al,
    const __nv_bfloat16* __restrict__ Bh, const __nv_bfloat16* __restrict__ Bl,
    const float* __restrict__ bias, float* __restrict__ C, int N)
{
    __shared__ __align__(16) __nv_bfloat16 sAh[128][BKP];
    __shared__ __align__(16) __nv_bfloat16 sAl[128][BKP];
    __shared__ __align__(16) __nv_bfloat16 sBh[128][BKP];
    __shared__ __align__(16) __nv_bfloat16 sBl[128][BKP];

    const int tid  = threadIdx.x;
    const int lane = tid & 31;
    const int wid  = tid >> 5;
    const int warp_m = (wid & 1) * 64;   // 0 or 64
    const int warp_n = (wid >> 1) * 32;  // 0,32,64,96
    const int brow = blockIdx.y * 128;
    const int bcol = blockIdx.x * 128;

    float acc[4][4][4];
#pragma unroll
    for (int mi = 0; mi < 4; mi++)
#pragma unroll
        for (int ni = 0; ni < 4; ni++)
#pragma unroll
            for (int j = 0; j < 4; j++) acc[mi][ni][j] = 0.0f;

    // ldmatrix source addresses (fixed per thread, advance by k-half)
    const int a_row = (lane & 7) + ((lane >> 3) & 1) * 8;  // 0..15
    const int a_kh  = (lane >> 4) * 8;                     // 0 or 8
    const int b_row = lane & 7;
    const int b_kh  = ((lane >> 3) & 1) * 8;

    for (int s = 0; s < KDIM / 32; s++) {
        // Load slab: A/B 128 rows x 32 bf16 = 4 uint4 per row, hi & lo
#pragma unroll
        for (int u = tid; u < 512; u += 256) {
            const int row = u >> 2;
            const int c8 = (u & 3) * 8;
            const size_t ga = (size_t)(brow + row) * KDIM + s * 32 + c8;
            *(uint4*)&sAh[row][c8] = *(const uint4*)&Ah[ga];
            *(uint4*)&sAl[row][c8] = *(const uint4*)&Al[ga];
            const size_t gb = (size_t)(bcol + row) * KDIM + s * 32 + c8;
            *(uint4*)&sBh[row][c8] = *(const uint4*)&Bh[gb];
            *(uint4*)&sBl[row][c8] = *(const uint4*)&Bl[gb];
        }
        __syncthreads();

#pragma unroll
        for (int kk = 0; kk < 2; kk++) {    // two k16 steps per slab
            const int k0 = kk * 16;
            uint32_t ah[4][4], al[4][4], bh[4][2], bl[4][2];
#pragma unroll
            for (int mi = 0; mi < 4; mi++) {
                const int r = warp_m + mi * 16 + a_row;
                ldmx4(ah[mi][0], ah[mi][1], ah[mi][2], ah[mi][3],
                      smem_u32(&sAh[r][k0 + a_kh]));
                ldmx4(al[mi][0], al[mi][1], al[mi][2], al[mi][3],
                      smem_u32(&sAl[r][k0 + a_kh]));
            }
#pragma unroll
            for (int ni = 0; ni < 4; ni++) {
                const int r = warp_n + ni * 8 + b_row;
                ldmx2(bh[ni][0], bh[ni][1], smem_u32(&sBh[r][k0 + b_kh]));
                ldmx2(bl[ni][0], bl[ni][1], smem_u32(&sBl[r][k0 + b_kh]));
            }
#pragma unroll
            for (int mi = 0; mi < 4; mi++)
#pragma unroll
                for (int ni = 0; ni < 4; ni++) {
                    mma_bf16(acc[mi][ni], ah[mi], bh[ni]);
                    mma_bf16(acc[mi][ni], ah[mi], bl[ni]);
                    mma_bf16(acc[mi][ni], al[mi], bh[ni]);
                }
        }
        __syncthreads();
    }

    // Epilogue: C fragment c0,c1 -> (row=lane>>2, col=(lane&3)*2), c2,c3 -> row+8
    const int er = brow + warp_m + (lane >> 2);
    const int ec = bcol + warp_n + (lane & 3) * 2;
#pragma unroll
    for (int mi = 0; mi < 4; mi++)
#pragma unroll
        for (int ni = 0; ni < 4; ni++) {
            const int r0 = er + mi * 16;
            const int c0 = ec + ni * 8;
            float2 v0, v1;
            v0.x = acc[mi][ni][0] + bias[c0];
            v0.y = acc[mi][ni][1] + bias[c0 + 1];
            v1.x = acc[mi][ni][2] + bias[c0];
            v1.y = acc[mi][ni][3] + bias[c0 + 1];
            *(float2*)&C[(size_t)r0 * N + c0] = v0;
            *(float2*)&C[(size_t)(r0 + 8) * N + c0] = v1;
        }
}

// ---------------------------------------------------------------------------
// Flash attention (fp32, causal) — unchanged from round 2 (validated).
// ---------------------------------------------------------------------------
#define ATTN_SMEM (4 * 64 * 65 * 4)

__global__ __launch_bounds__(128) void flash_attn_kernel()
{
    extern __shared__ float fsmem[];
    float* Qs = fsmem;
    float* Ks = Qs + 64 * 65;
    float* Vs = Ks + 64 * 65;
    float* Ps = Vs + 64 * 65;

    const float* qkv = g_qkv;
    const int qt = blockIdx.x;
    const int h  = blockIdx.y;
    const int b  = blockIdx.z;
    const int tid = threadIdx.x;
    const int tr = tid >> 3;
    const int tc = tid & 7;

    const size_t row0 = (size_t)b * SEQ + qt * 64;
    const float* qbase = qkv + row0 * QKV_N + h * HD;

    for (int u = tid; u < 64 * 16; u += 128) {
        const int r = u >> 4;
        const int c4 = (u & 15) * 4;
        float4 v = *(const float4*)&qbase[(size_t)r * QKV_N + c4];
        float* dst = &Qs[r * 65 + c4];
        dst[0] = v.x; dst[1] = v.y; dst[2] = v.z; dst[3] = v.w;
    }

    float m_i[4], l_i[4], acc[4][8];
#pragma unroll
    for (int i = 0; i < 4; i++) {
        m_i[i] = -1e30f; l_i[i] = 0.0f;
#pragma unroll
        for (int d = 0; d < 8; d++) acc[i][d] = 0.0f;
    }

    const float scale = 0.03125f;

    for (int kt = 0; kt <= qt; kt++) {
        const size_t krow0 = (size_t)b * SEQ + kt * 64;
        const float* kbase = qkv + krow0 * QKV_N + DM + h * HD;
        const float* vbase = qkv + krow0 * QKV_N + 2 * DM + h * HD;
        for (int u = tid; u < 64 * 16; u += 128) {
            const int r = u >> 4;
            const int c4 = (u & 15) * 4;
            float4 kv = *(const float4*)&kbase[(size_t)r * QKV_N + c4];
            float* kd = &Ks[r * 65 + c4];
            kd[0] = kv.x; kd[1] = kv.y; kd[2] = kv.z; kd[3] = kv.w;
            float4 vv = *(const float4*)&vbase[(size_t)r * QKV_N + c4];
            float* vd = &Vs[r * 65 + c4];
            vd[0] = vv.x; vd[1] = vv.y; vd[2] = vv.z; vd[3] = vv.w;
        }
        __syncthreads();

        float s[4][8];
#pragma unroll
        for (int i = 0; i < 4; i++)
#pragma unroll
            for (int j = 0; j < 8; j++) s[i][j] = 0.0f;

        for (int d = 0; d < 64; d++) {
            float qv[4], kv[8];
#pragma unroll
            for (int i = 0; i < 4; i++) qv[i] = Qs[(tr * 4 + i) * 65 + d];
#pragma unroll
            for (int j = 0; j < 8; j++) kv[j] = Ks[(tc * 8 + j) * 65 + d];
#pragma unroll
            for (int i = 0; i < 4; i++)
#pragma unroll
                for (int j = 0; j < 8; j++) s[i][j] = fmaf(qv[i], kv[j], s[i][j]);
        }

        const bool diag = (kt == qt);
#pragma unroll
        for (int i = 0; i < 4; i++) {
            const int qi = tr * 4 + i;
#pragma unroll
            for (int j = 0; j < 8; j++) {
                const int kj = tc * 8 + j;
                s[i][j] *= scale;
                if (diag && kj > qi) s[i][j] = -1e30f;
            }
        }

#pragma unroll
        for (int i = 0; i < 4; i++) {
            float mt = s[i][0];
#pragma unroll
            for (int j = 1; j < 8; j++) mt = fmaxf(mt, s[i][j]);
            mt = fmaxf(mt, __shfl_xor_sync(0xffffffffu, mt, 1));
            mt = fmaxf(mt, __shfl_xor_sync(0xffffffffu, mt, 2));
            mt = fmaxf(mt, __shfl_xor_sync(0xffffffffu, mt, 4));

            const float m_new = fmaxf(m_i[i], mt);
            const float alpha = __expf(m_i[i] - m_new);
            float ls = 0.0f;
#pragma unroll
            for (int j = 0; j < 8; j++) {
                const float p = __expf(s[i][j] - m_new);
                s[i][j] = p;
                ls += p;
            }
            ls += __shfl_xor_sync(0xffffffffu, ls, 1);
            ls += __shfl_xor_sync(0xffffffffu, ls, 2);
            ls += __shfl_xor_sync(0xffffffffu, ls, 4);

            l_i[i] = l_i[i] * alpha + ls;
            m_i[i] = m_new;
#pragma unroll
            for (int d = 0; d < 8; d++) acc[i][d] *= alpha;
#pragma unroll
            for (int j = 0; j < 8; j++)
                Ps[(tr * 4 + i) * 65 + tc * 8 + j] = s[i][j];
        }
        __syncthreads();

        for (int j = 0; j < 64; j++) {
            float pv[4], vv[8];
#pragma unroll
            for (int i = 0; i < 4; i++) pv[i] = Ps[(tr * 4 + i) * 65 + j];
#pragma unroll
            for (int d = 0; d < 8; d++) vv[d] = Vs[j * 65 + tc * 8 + d];
#pragma unroll
            for (int i = 0; i < 4; i++)
#pragma unroll
                for (int d = 0; d < 8; d++) acc[i][d] = fmaf(pv[i], vv[d], acc[i][d]);
        }
        __syncthreads();
    }

#pragma unroll
    for (int i = 0; i < 4; i++) {
        const float inv = 1.0f / l_i[i];
        const size_t row = row0 + tr * 4 + i;
        float* dst = &g_attn[row * DM + h * HD + tc * 8];
        float4 r0, r1;
        r0.x = acc[i][0] * inv; r0.y = acc[i][1] * inv;
        r0.z = acc[i][2] * inv; r0.w = acc[i][3] * inv;
        r1.x = acc[i][4] * inv; r1.y = acc[i][5] * inv;
        r1.z = acc[i][6] * inv; r1.w = acc[i][7] * inv;
        *(float4*)&dst[0] = r0;
        *(float4*)&dst[4] = r1;
    }
}

// ---------------------------------------------------------------------------
// Launcher
// ---------------------------------------------------------------------------
extern "C" void kernel_launch(void* const* d_in, const int* in_sizes, int n_in,
                              void* d_out, int out_size)
{
    const float* x     = (const float*)d_in[0];
    const float* w_qkv = (const float*)d_in[1];
    const float* b_qkv = (const float*)d_in[2];
    const float* w_out = (const float*)d_in[3];
    const float* b_out = (const float*)d_in[4];
    float* out = (float*)d_out;

    float *qkv_ptr, *attn_ptr;
    __nv_bfloat16 *xh, *xl, *wqh, *wql, *woh, *wol, *ath, *atl;
    cudaGetSymbolAddress((void**)&qkv_ptr, g_qkv);
    cudaGetSymbolAddress((void**)&attn_ptr, g_attn);
    cudaGetSymbolAddress((void**)&xh, g_x_hi);
    cudaGetSymbolAddress((void**)&xl, g_x_lo);
    cudaGetSymbolAddress((void**)&wqh, g_wq_hi);
    cudaGetSymbolAddress((void**)&wql, g_wq_lo);
    cudaGetSymbolAddress((void**)&woh, g_wo_hi);
    cudaGetSymbolAddress((void**)&wol, g_wo_lo);
    cudaGetSymbolAddress((void**)&ath, g_at_hi);
    cudaGetSymbolAddress((void**)&atl, g_at_lo);

    cudaFuncSetAttribute(flash_attn_kernel,
                         cudaFuncAttributeMaxDynamicSharedMemorySize, ATTN_SMEM);

    // Splits / transposes
    split_f32<<<(MROWS * KDIM / 4 + 255) / 256, 256>>>(x, xh, xl, MROWS * KDIM);
    transpose_split<<<dim3(QKV_N / 32, KDIM / 32), dim3(32, 8)>>>(w_qkv, wqh, wql, KDIM, QKV_N);
    transpose_split<<<dim3(DM / 32, KDIM / 32), dim3(32, 8)>>>(w_out, woh, wol, KDIM, DM);

    // 1) QKV = x @ w_qkv + b_qkv  (split-bf16 mma.sync)
    gemm_mma<<<dim3(QKV_N / 128, MROWS / 128), 256>>>(
        xh, xl, wqh, wql, b_qkv, qkv_ptr, QKV_N);

    // 2) Attention: g_qkv -> g_attn (fp32)
    flash_attn_kernel<<<dim3(SEQ / 64, NH, BSZ), 128, ATTN_SMEM>>>();

    // 3) Split attention output, then out = attn @ w_out + b_out
    split_f32<<<(MROWS * DM / 4 + 255) / 256, 256>>>(attn_ptr, ath, atl, MROWS * DM);
    gemm_mma<<<dim3(DM / 128, MROWS / 128), 256>>>(
        ath, atl, woh, wol, b_out, out, DM);
}

// round 5
// speedup vs baseline: 2.5033x; 1.8497x over previous
#include <cuda_runtime.h>
#include <cuda_bf16.h>
#include <cstdint>

// Problem constants
#define BSZ 2
#define SEQ 2048
#define DM 1024
#define NH 16
#define HD 64
#define MROWS 4096
#define QKV_N 3072
#define KDIM 1024

// ---------------------------------------------------------------------------
// Scratch (__device__ globals; allocation-free rule)
// ---------------------------------------------------------------------------
__device__ __align__(16) __nv_bfloat16 g_x_hi[MROWS * KDIM];
__device__ __align__(16) __nv_bfloat16 g_x_lo[MROWS * KDIM];
__device__ __align__(16) __nv_bfloat16 g_wq_hi[QKV_N * KDIM];  // w_qkv^T [3072,1024]
__device__ __align__(16) __nv_bfloat16 g_wq_lo[QKV_N * KDIM];
__device__ __align__(16) __nv_bfloat16 g_wo_hi[DM * KDIM];     // w_out^T [1024,1024]
__device__ __align__(16) __nv_bfloat16 g_wo_lo[DM * KDIM];
__device__ __align__(16) __nv_bfloat16 g_qkvh[MROWS * QKV_N];  // qkv hi (Q pre-scaled 1/32)
__device__ __align__(16) __nv_bfloat16 g_qkvl[MROWS * QKV_N];  // qkv lo
__device__ __align__(16) __nv_bfloat16 g_ath[MROWS * DM];      // attn out hi
__device__ __align__(16) __nv_bfloat16 g_atl[MROWS * DM];      // attn out lo

// ---------------------------------------------------------------------------
// mma.sync / ldmatrix helpers (sm_80-compatible PTX)
// ---------------------------------------------------------------------------
__device__ __forceinline__ uint32_t smem_u32(const void* p) {
    uint32_t a;
    asm("{ .reg .u64 t; cvta.to.shared.u64 t, %1; cvt.u32.u64 %0, t; }" : "=r"(a) : "l"(p));
    return a;
}
__device__ __forceinline__ void ldmx4(uint32_t& r0, uint32_t& r1, uint32_t& r2,
                                      uint32_t& r3, uint32_t addr) {
    asm volatile("ldmatrix.sync.aligned.m8n8.x4.shared.b16 {%0,%1,%2,%3}, [%4];"
                 : "=r"(r0), "=r"(r1), "=r"(r2), "=r"(r3) : "r"(addr));
}
__device__ __forceinline__ void ldmx2(uint32_t& r0, uint32_t& r1, uint32_t addr) {
    asm volatile("ldmatrix.sync.aligned.m8n8.x2.shared.b16 {%0,%1}, [%2];"
                 : "=r"(r0), "=r"(r1) : "r"(addr));
}
__device__ __forceinline__ void ldmx2t(uint32_t& r0, uint32_t& r1, uint32_t addr) {
    asm volatile("ldmatrix.sync.aligned.m8n8.x2.trans.shared.b16 {%0,%1}, [%2];"
                 : "=r"(r0), "=r"(r1) : "r"(addr));
}
__device__ __forceinline__ void mma_bf16(float* c, const uint32_t* a, const uint32_t* b) {
    asm volatile(
        "mma.sync.aligned.m16n8k16.row.col.f32.bf16.bf16.f32 "
        "{%0,%1,%2,%3}, {%4,%5,%6,%7}, {%8,%9}, {%0,%1,%2,%3};"
        : "+f"(c[0]), "+f"(c[1]), "+f"(c[2]), "+f"(c[3])
        : "r"(a[0]), "r"(a[1]), "r"(a[2]), "r"(a[3]), "r"(b[0]), "r"(b[1]));
}
__device__ __forceinline__ uint32_t pack2bf(__nv_bfloat16 a, __nv_bfloat16 b) {
    __nv_bfloat162 t = __halves2bfloat162(a, b);
    return *reinterpret_cast<uint32_t*>(&t);
}
// Split two fp32 into packed hi/lo bf16x2
__device__ __forceinline__ void split2(float a, float b, uint32_t& hi, uint32_t& lo) {
    __nv_bfloat16 ha = __float2bfloat16(a), hb = __float2bfloat16(b);
    hi = pack2bf(ha, hb);
    lo = pack2bf(__float2bfloat16(a - __bfloat162float(ha)),
                 __float2bfloat16(b - __bfloat162float(hb)));
}

// ---------------------------------------------------------------------------
// Split fp32 -> bf16 hi/lo (same layout), vectorized x4
// ---------------------------------------------------------------------------
__global__ __launch_bounds__(256) void split_f32(
    const float* __restrict__ src, __nv_bfloat16* __restrict__ hi,
    __nv_bfloat16* __restrict__ lo, int n)
{
    int i = (blockIdx.x * 256 + threadIdx.x) * 4;
    if (i >= n) return;
    float4 v = *(const float4*)&src[i];
    uint32_t h0, l0, h1, l1;
    split2(v.x, v.y, h0, l0);
    split2(v.z, v.w, h1, l1);
    *(uint2*)&hi[i] = make_uint2(h0, h1);
    *(uint2*)&lo[i] = make_uint2(l0, l1);
}

// ---------------------------------------------------------------------------
// Transpose + split: w [K, N] fp32 row-major -> th/tl [N, K] bf16
// ---------------------------------------------------------------------------
__global__ __launch_bounds__(256) void transpose_split(
    const float* __restrict__ w, __nv_bfloat16* __restrict__ th,
    __nv_bfloat16* __restrict__ tl, int K, int N)
{
    __shared__ float tile[32][33];
    const int nx = blockIdx.x * 32 + threadIdx.x;
    const int k0 = blockIdx.y * 32;
#pragma unroll
    for (int j = 0; j < 32; j += 8)
        tile[threadIdx.y + j][threadIdx.x] = w[(size_t)(k0 + threadIdx.y + j) * N + nx];
    __syncthreads();
    const int kx = k0 + threadIdx.x;
    const int n0 = blockIdx.x * 32;
#pragma unroll
    for (int j = 0; j < 32; j += 8) {
        float v = tile[threadIdx.x][threadIdx.y + j];
        __nv_bfloat16 h = __float2bfloat16(v);
        th[(size_t)(n0 + threadIdx.y + j) * K + kx] = h;
        tl[(size_t)(n0 + threadIdx.y + j) * K + kx] = __float2bfloat16(v - __bfloat162float(h));
    }
}

// ---------------------------------------------------------------------------
// Shared GEMM mainloop (128x128 CTA, BK=32, 8 warps, warp 64x32), validated R4.
// Produces acc[4][4][4]; epilogue differs per kernel.
// ---------------------------------------------------------------------------
#define BKP 40

#define GEMM_MAINLOOP(Ah, Al, Bh, Bl)                                              \
    __shared__ __align__(16) __nv_bfloat16 sAh[128][BKP];                          \
    __shared__ __align__(16) __nv_bfloat16 sAl[128][BKP];                          \
    __shared__ __align__(16) __nv_bfloat16 sBh[128][BKP];                          \
    __shared__ __align__(16) __nv_bfloat16 sBl[128][BKP];                          \
    const int tid  = threadIdx.x;                                                  \
    const int lane = tid & 31;                                                     \
    const int wid  = tid >> 5;                                                     \
    const int warp_m = (wid & 1) * 64;                                             \
    const int warp_n = (wid >> 1) * 32;                                            \
    const int brow = blockIdx.y * 128;                                             \
    const int bcol = blockIdx.x * 128;                                             \
    float acc[4][4][4];                                                            \
    _Pragma("unroll") for (int mi = 0; mi < 4; mi++)                               \
        _Pragma("unroll") for (int ni = 0; ni < 4; ni++)                           \
            _Pragma("unroll") for (int j = 0; j < 4; j++) acc[mi][ni][j] = 0.0f;   \
    const int a_row = (lane & 7) + ((lane >> 3) & 1) * 8;                          \
    const int a_kh  = (lane >> 4) * 8;                                             \
    const int b_row = lane & 7;                                                    \
    const int b_kh  = ((lane >> 3) & 1) * 8;                                       \
    for (int s = 0; s < KDIM / 32; s++) {                                          \
        _Pragma("unroll") for (int u = tid; u < 512; u += 256) {                   \
            const int row = u >> 2;                                                \
            const int c8 = (u & 3) * 8;                                            \
            const size_t ga = (size_t)(brow + row) * KDIM + s * 32 + c8;           \
            *(uint4*)&sAh[row][c8] = *(const uint4*)&Ah[ga];                       \
            *(uint4*)&sAl[row][c8] = *(const uint4*)&Al[ga];                       \
            const size_t gb = (size_t)(bcol + row) * KDIM + s * 32 + c8;           \
            *(uint4*)&sBh[row][c8] = *(const uint4*)&Bh[gb];                       \
            *(uint4*)&sBl[row][c8] = *(const uint4*)&Bl[gb];                       \
        }                                                                          \
        __syncthreads();                                                           \
        _Pragma("unroll") for (int kk = 0; kk < 2; kk++) {                         \
            const int k0 = kk * 16;                                                \
            uint32_t ah[4][4], al[4][4], bh[4][2], bl[4][2];                       \
            _Pragma("unroll") for (int mi = 0; mi < 4; mi++) {                     \
                const int r = warp_m + mi * 16 + a_row;                            \
                ldmx4(ah[mi][0], ah[mi][1], ah[mi][2], ah[mi][3],                  \
                      smem_u32(&sAh[r][k0 + a_kh]));                               \
                ldmx4(al[mi][0], al[mi][1], al[mi][2], al[mi][3],                  \
                      smem_u32(&sAl[r][k0 + a_kh]));                               \
            }                                                                      \
            _Pragma("unroll") for (int ni = 0; ni < 4; ni++) {                     \
                const int r = warp_n + ni * 8 + b_row;                             \
                ldmx2(bh[ni][0], bh[ni][1], smem_u32(&sBh[r][k0 + b_kh]));         \
                ldmx2(bl[ni][0], bl[ni][1], smem_u32(&sBl[r][k0 + b_kh]));         \
            }                                                                      \
            _Pragma("unroll") for (int mi = 0; mi < 4; mi++)                       \
                _Pragma("unroll") for (int ni = 0; ni < 4; ni++) {                 \
                    mma_bf16(acc[mi][ni], ah[mi], bh[ni]);                         \
                    mma_bf16(acc[mi][ni], ah[mi], bl[ni]);                         \
                    mma_bf16(acc[mi][ni], al[mi], bh[ni]);                         \
                }                                                                  \
        }                                                                          \
        __syncthreads();                                                           \
    }

// GEMM -> fp32 C + bias (out-projection)
__global__ __launch_bounds__(256) void gemm_mma_f32(
    const __nv_bfloat16* __restrict__ Ah, const __nv_bfloat16* __restrict__ Al,
    const __nv_bfloat16* __restrict__ Bh, const __nv_bfloat16* __restrict__ Bl,
    const float* __restrict__ bias, float* __restrict__ C, int N)
{
    GEMM_MAINLOOP(Ah, Al, Bh, Bl)
    const int er = brow + warp_m + (lane >> 2);
    const int ec = bcol + warp_n + (lane & 3) * 2;
#pragma unroll
    for (int mi = 0; mi < 4; mi++)
#pragma unroll
        for (int ni = 0; ni < 4; ni++) {
            const int r0 = er + mi * 16;
            const int c0 = ec + ni * 8;
            float2 v0, v1;
            v0.x = acc[mi][ni][0] + bias[c0];
            v0.y = acc[mi][ni][1] + bias[c0 + 1];
            v1.x = acc[mi][ni][2] + bias[c0];
            v1.y = acc[mi][ni][3] + bias[c0 + 1];
            *(float2*)&C[(size_t)r0 * N + c0] = v0;
            *(float2*)&C[(size_t)(r0 + 8) * N + c0] = v1;
        }
}

// GEMM -> bf16 hi/lo + bias, cols < DM (Q section) pre-scaled by 1/32 (QKV proj)
__global__ __launch_bounds__(256) void gemm_mma_qkv(
    const __nv_bfloat16* __restrict__ Ah, const __nv_bfloat16* __restrict__ Al,
    const __nv_bfloat16* __restrict__ Bh, const __nv_bfloat16* __restrict__ Bl,
    const float* __restrict__ bias,
    __nv_bfloat16* __restrict__ Ch, __nv_bfloat16* __restrict__ Cl, int N)
{
    GEMM_MAINLOOP(Ah, Al, Bh, Bl)
    const int er = brow + warp_m + (lane >> 2);
    const int ec = bcol + warp_n + (lane & 3) * 2;
#pragma unroll
    for (int mi = 0; mi < 4; mi++)
#pragma unroll
        for (int ni = 0; ni < 4; ni++) {
            const int r0 = er + mi * 16;
            const int c0 = ec + ni * 8;
            const float sc = (c0 < DM) ? 0.03125f : 1.0f;
            float v0 = (acc[mi][ni][0] + bias[c0]) * sc;
            float v1 = (acc[mi][ni][1] + bias[c0 + 1]) * sc;
            float v2 = (acc[mi][ni][2] + bias[c0]) * sc;
            float v3 = (acc[mi][ni][3] + bias[c0 + 1]) * sc;
            uint32_t h01, l01, h23, l23;
            split2(v0, v1, h01, l01);
            split2(v2, v3, h23, l23);
            *(uint32_t*)&Ch[(size_t)r0 * N + c0] = h01;
            *(uint32_t*)&Cl[(size_t)r0 * N + c0] = l01;
            *(uint32_t*)&Ch[(size_t)(r0 + 8) * N + c0] = h23;
            *(uint32_t*)&Cl[(size_t)(r0 + 8) * N + c0] = l23;
        }
}

// ---------------------------------------------------------------------------
// Flash attention, split-bf16 mma.sync (FA2 register layout).
// CTA = (128-q-row tile, head, batch); 8 warps x 16 q-rows.
// K/V tiles: 64 tokens, smem hi/lo padded rows (72 elems = 144B: conflict-free
// for both ldmatrix (K) and ldmatrix.trans (V)).
// Q pre-scaled by 1/32 at the QKV epilogue, so S = Qs K^T is final logits.
// ---------------------------------------------------------------------------
__global__ __launch_bounds__(256) void flash_attn_mma()
{
    __shared__ __align__(16) __nv_bfloat16 sKh[64][72], sKl[64][72];
    __shared__ __align__(16) __nv_bfloat16 sVh[64][72], sVl[64][72];

    const int tid = threadIdx.x, lane = tid & 31, wid = tid >> 5;
    const int qt = blockIdx.x, h = blockIdx.y, b = blockIdx.z;
    const int q0 = qt * 128;
    const size_t rowb = (size_t)b * SEQ + q0;
    const int wm = wid * 16;
    const int ra = lane >> 2;          // 0..7
    const int kq = (lane & 3) * 2;     // 0,2,4,6

    // --- Preload Q a-frags straight from global (fragment layout addressing) ---
    uint32_t qfh[4][4], qfl[4][4];
    {
        const size_t r0 = (rowb + wm + ra) * QKV_N + h * HD;
        const size_t r1 = (rowb + wm + ra + 8) * QKV_N + h * HD;
#pragma unroll
        for (int ks = 0; ks < 4; ks++) {
            const int c = ks * 16 + kq;
            qfh[ks][0] = *(const uint32_t*)&g_qkvh[r0 + c];
            qfh[ks][1] = *(const uint32_t*)&g_qkvh[r1 + c];
            qfh[ks][2] = *(const uint32_t*)&g_qkvh[r0 + c + 8];
            qfh[ks][3] = *(const uint32_t*)&g_qkvh[r1 + c + 8];
            qfl[ks][0] = *(const uint32_t*)&g_qkvl[r0 + c];
            qfl[ks][1] = *(const uint32_t*)&g_qkvl[r1 + c];
            qfl[ks][2] = *(const uint32_t*)&g_qkvl[r0 + c + 8];
            qfl[ks][3] = *(const uint32_t*)&g_qkvl[r1 + c + 8];
        }
    }

    float o[8][4];
#pragma unroll
    for (int dn = 0; dn < 8; dn++)
#pragma unroll
        for (int j = 0; j < 4; j++) o[dn][j] = 0.0f;
    float m_lo = -1e30f, m_hi = -1e30f, l_lo = 0.0f, l_hi = 0.0f;

    const int b_row = lane & 7;
    const int b_kh = ((lane >> 3) & 1) * 8;
    const int v_row = lane & 15;

    const int nkt = 2 * qt + 2;
    for (int kt = 0; kt < nkt; kt++) {
        const int t0 = kt * 64;
        // Load K/V tile (hi/lo): 64 rows x 64 bf16 each
        const size_t gr = (size_t)b * SEQ + t0;
        for (int u = tid; u < 512; u += 256) {
            const int row = u >> 3;
            const int c8 = (u & 7) * 8;
            const size_t gk = (gr + row) * QKV_N + DM + h * HD + c8;
            const size_t gv = (gr + row) * QKV_N + 2 * DM + h * HD + c8;
            *(uint4*)&sKh[row][c8] = *(const uint4*)&g_qkvh[gk];
            *(uint4*)&sKl[row][c8] = *(const uint4*)&g_qkvl[gk];
            *(uint4*)&sVh[row][c8] = *(const uint4*)&g_qkvh[gv];
            *(uint4*)&sVl[row][c8] = *(const uint4*)&g_qkvl[gv];
        }
        __syncthreads();

        // --- S = Q K^T (3-term split) ---
        float s[8][4];
#pragma unroll
        for (int nt = 0; nt < 8; nt++)
#pragma unroll
            for (int j = 0; j < 4; j++) s[nt][j] = 0.0f;
#pragma unroll
        for (int nt = 0; nt < 8; nt++) {
#pragma unroll
            for (int ks = 0; ks < 4; ks++) {
                uint32_t bh[2], bl[2];
                ldmx2(bh[0], bh[1], smem_u32(&sKh[nt * 8 + b_row][ks * 16 + b_kh]));
                ldmx2(bl[0], bl[1], smem_u32(&sKl[nt * 8 + b_row][ks * 16 + b_kh]));
                mma_bf16(s[nt], qfh[ks], bh);
                mma_bf16(s[nt], qfh[ks], bl);
                mma_bf16(s[nt], qfl[ks], bh);
            }
        }

        // --- Causal mask (only when tile can cross this warp's diagonal) ---
        if (t0 + 63 > q0 + wm) {
            const int row_lo = q0 + wm + ra;
            const int row_hi = row_lo + 8;
#pragma unroll
            for (int nt = 0; nt < 8; nt++) {
                const int c = t0 + nt * 8 + kq;
                if (c > row_lo) s[nt][0] = -1e30f;
                if (c + 1 > row_lo) s[nt][1] = -1e30f;
                if (c > row_hi) s[nt][2] = -1e30f;
                if (c + 1 > row_hi) s[nt][3] = -1e30f;
            }
        }

        // --- Online softmax, row r (regs 0,1) and row r+8 (regs 2,3) ---
        {
            float mt0 = -1e30f, mt1 = -1e30f;
#pragma unroll
            for (int nt = 0; nt < 8; nt++) {
                mt0 = fmaxf(mt0, fmaxf(s[nt][0], s[nt][1]));
                mt1 = fmaxf(mt1, fmaxf(s[nt][2], s[nt][3]));
            }
            mt0 = fmaxf(mt0, __shfl_xor_sync(0xffffffffu, mt0, 1));
            mt0 = fmaxf(mt0, __shfl_xor_sync(0xffffffffu, mt0, 2));
            mt1 = fmaxf(mt1, __shfl_xor_sync(0xffffffffu, mt1, 1));
            mt1 = fmaxf(mt1, __shfl_xor_sync(0xffffffffu, mt1, 2));
            const float mn0 = fmaxf(m_lo, mt0);
            const float mn1 = fmaxf(m_hi, mt1);
            const float al0 = __expf(m_lo - mn0);
            const float al1 = __expf(m_hi - mn1);
            float ls0 = 0.0f, ls1 = 0.0f;
#pragma unroll
            for (int nt = 0; nt < 8; nt++) {
                s[nt][0] = __expf(s[nt][0] - mn0);
                s[nt][1] = __expf(s[nt][1] - mn0);
                s[nt][2] = __expf(s[nt][2] - mn1);
                s[nt][3] = __expf(s[nt][3] - mn1);
                ls0 += s[nt][0] + s[nt][1];
                ls1 += s[nt][2] + s[nt][3];
            }
            ls0 += __shfl_xor_sync(0xffffffffu, ls0, 1);
            ls0 += __shfl_xor_sync(0xffffffffu, ls0, 2);
            ls1 += __shfl_xor_sync(0xffffffffu, ls1, 1);
            ls1 += __shfl_xor_sync(0xffffffffu, ls1, 2);
            l_lo = l_lo * al0 + ls0;
            l_hi = l_hi * al1 + ls1;
            m_lo = mn0; m_hi = mn1;
#pragma unroll
            for (int dn = 0; dn < 8; dn++) {
                o[dn][0] *= al0; o[dn][1] *= al0;
                o[dn][2] *= al1; o[dn][3] *= al1;
            }
        }

        // --- Re-pack P (c-frag -> a-frag identity) with hi/lo split ---
        uint32_t ph[4][4], pl[4][4];
#pragma unroll
        for (int j = 0; j < 4; j++) {
            split2(s[2 * j][0], s[2 * j][1], ph[j][0], pl[j][0]);
            split2(s[2 * j][2], s[2 * j][3], ph[j][1], pl[j][1]);
            split2(s[2 * j + 1][0], s[2 * j + 1][1], ph[j][2], pl[j][2]);
            split2(s[2 * j + 1][2], s[2 * j + 1][3], ph[j][3], pl[j][3]);
        }

        // --- O += P V (3-term split), V b-frags via ldmatrix.trans ---
#pragma unroll
        for (int dn = 0; dn < 8; dn++) {
#pragma unroll
            for (int j = 0; j < 4; j++) {
                uint32_t vh[2], vl[2];
                ldmx2t(vh[0], vh[1], smem_u32(&sVh[j * 16 + v_row][dn * 8]));
                ldmx2t(vl[0], vl[1], smem_u32(&sVl[j * 16 + v_row][dn * 8]));
                mma_bf16(o[dn], ph[j], vh);
                mma_bf16(o[dn], ph[j], vl);
                mma_bf16(o[dn], pl[j], vh);
            }
        }
        __syncthreads();
    }

    // --- Finalize: normalize, split hi/lo, write for the out-proj GEMM ---
    const float il = 1.0f / l_lo;
    const float ih = 1.0f / l_hi;
    const size_t row_lo_g = rowb + wm + ra;
    const size_t row_hi_g = row_lo_g + 8;
#pragma unroll
    for (int dn = 0; dn < 8; dn++) {
        const int col = h * HD + dn * 8 + kq;
        uint32_t h01, l01, h23, l23;
        split2(o[dn][0] * il, o[dn][1] * il, h01, l01);
        split2(o[dn][2] * ih, o[dn][3] * ih, h23, l23);
        *(uint32_t*)&g_ath[row_lo_g * DM + col] = h01;
        *(uint32_t*)&g_atl[row_lo_g * DM + col] = l01;
        *(uint32_t*)&g_ath[row_hi_g * DM + col] = h23;
        *(uint32_t*)&g_atl[row_hi_g * DM + col] = l23;
    }
}

// ---------------------------------------------------------------------------
// Launcher
// ---------------------------------------------------------------------------
extern "C" void kernel_launch(void* const* d_in, const int* in_sizes, int n_in,
                              void* d_out, int out_size)
{
    const float* x     = (const float*)d_in[0];
    const float* w_qkv = (const float*)d_in[1];
    const float* b_qkv = (const float*)d_in[2];
    const float* w_out = (const float*)d_in[3];
    const float* b_out = (const float*)d_in[4];
    float* out = (float*)d_out;

    __nv_bfloat16 *xh, *xl, *wqh, *wql, *woh, *wol, *qh, *ql, *ath, *atl;
    cudaGetSymbolAddress((void**)&xh, g_x_hi);
    cudaGetSymbolAddress((void**)&xl, g_x_lo);
    cudaGetSymbolAddress((void**)&wqh, g_wq_hi);
    cudaGetSymbolAddress((void**)&wql, g_wq_lo);
    cudaGetSymbolAddress((void**)&woh, g_wo_hi);
    cudaGetSymbolAddress((void**)&wol, g_wo_lo);
    cudaGetSymbolAddress((void**)&qh, g_qkvh);
    cudaGetSymbolAddress((void**)&ql, g_qkvl);
    cudaGetSymbolAddress((void**)&ath, g_ath);
    cudaGetSymbolAddress((void**)&atl, g_atl);

    // Preprocessing
    split_f32<<<(MROWS * KDIM / 4 + 255) / 256, 256>>>(x, xh, xl, MROWS * KDIM);
    transpose_split<<<dim3(QKV_N / 32, KDIM / 32), dim3(32, 8)>>>(w_qkv, wqh, wql, KDIM, QKV_N);
    transpose_split<<<dim3(DM / 32, KDIM / 32), dim3(32, 8)>>>(w_out, woh, wol, KDIM, DM);

    // 1) QKV projection -> bf16 hi/lo, Q section pre-scaled by 1/32
    gemm_mma_qkv<<<dim3(QKV_N / 128, MROWS / 128), 256>>>(
        xh, xl, wqh, wql, b_qkv, qh, ql, QKV_N);

    // 2) Attention (split-bf16 mma) -> g_ath/g_atl
    flash_attn_mma<<<dim3(SEQ / 128, NH, BSZ), 256>>>();

    // 3) Out projection -> fp32 output
    gemm_mma_f32<<<dim3(DM / 128, MROWS / 128), 256>>>(
        ath, atl, woh, wol, b_out, out, DM);
}

// round 6
// speedup vs baseline: 2.6486x; 1.0581x over previous
#include <cuda_runtime.h>
#include <cuda_bf16.h>
#include <cstdint>

// Problem constants
#define BSZ 2
#define SEQ 2048
#define DM 1024
#define NH 16
#define HD 64
#define MROWS 4096
#define QKV_N 3072
#define KDIM 1024

// ---------------------------------------------------------------------------
// Scratch (__device__ globals; allocation-free rule)
// ---------------------------------------------------------------------------
__device__ __align__(16) __nv_bfloat16 g_x_hi[MROWS * KDIM];
__device__ __align__(16) __nv_bfloat16 g_x_lo[MROWS * KDIM];
__device__ __align__(16) __nv_bfloat16 g_wq_hi[QKV_N * KDIM];  // w_qkv^T [3072,1024]
__device__ __align__(16) __nv_bfloat16 g_wq_lo[QKV_N * KDIM];
__device__ __align__(16) __nv_bfloat16 g_wo_hi[DM * KDIM];     // w_out^T [1024,1024]
__device__ __align__(16) __nv_bfloat16 g_wo_lo[DM * KDIM];
__device__ __align__(16) __nv_bfloat16 g_qkvh[MROWS * QKV_N];  // qkv hi (Q pre-scaled 1/32)
__device__ __align__(16) __nv_bfloat16 g_qkvl[MROWS * QKV_N];  // qkv lo
__device__ __align__(16) __nv_bfloat16 g_ath[MROWS * DM];      // attn out hi
__device__ __align__(16) __nv_bfloat16 g_atl[MROWS * DM];      // attn out lo

// ---------------------------------------------------------------------------
// mma.sync / ldmatrix / cp.async helpers (sm_80-compatible PTX)
// ---------------------------------------------------------------------------
__device__ __forceinline__ uint32_t smem_u32(const void* p) {
    uint32_t a;
    asm("{ .reg .u64 t; cvta.to.shared.u64 t, %1; cvt.u32.u64 %0, t; }" : "=r"(a) : "l"(p));
    return a;
}
__device__ __forceinline__ void ldmx4(uint32_t& r0, uint32_t& r1, uint32_t& r2,
                                      uint32_t& r3, uint32_t addr) {
    asm volatile("ldmatrix.sync.aligned.m8n8.x4.shared.b16 {%0,%1,%2,%3}, [%4];"
                 : "=r"(r0), "=r"(r1), "=r"(r2), "=r"(r3) : "r"(addr));
}
__device__ __forceinline__ void ldmx2(uint32_t& r0, uint32_t& r1, uint32_t addr) {
    asm volatile("ldmatrix.sync.aligned.m8n8.x2.shared.b16 {%0,%1}, [%2];"
                 : "=r"(r0), "=r"(r1) : "r"(addr));
}
__device__ __forceinline__ void ldmx2t(uint32_t& r0, uint32_t& r1, uint32_t addr) {
    asm volatile("ldmatrix.sync.aligned.m8n8.x2.trans.shared.b16 {%0,%1}, [%2];"
                 : "=r"(r0), "=r"(r1) : "r"(addr));
}
__device__ __forceinline__ void mma_bf16(float* c, const uint32_t* a, const uint32_t* b) {
    asm volatile(
        "mma.sync.aligned.m16n8k16.row.col.f32.bf16.bf16.f32 "
        "{%0,%1,%2,%3}, {%4,%5,%6,%7}, {%8,%9}, {%0,%1,%2,%3};"
        : "+f"(c[0]), "+f"(c[1]), "+f"(c[2]), "+f"(c[3])
        : "r"(a[0]), "r"(a[1]), "r"(a[2]), "r"(a[3]), "r"(b[0]), "r"(b[1]));
}
__device__ __forceinline__ void cp_async16(uint32_t saddr, const void* g) {
    asm volatile("cp.async.cg.shared.global [%0], [%1], 16;" :: "r"(saddr), "l"(g));
}
#define CP_COMMIT() asm volatile("cp.async.commit_group;" ::: "memory")
#define CP_WAIT(n)  asm volatile("cp.async.wait_group %0;" :: "n"(n) : "memory")

__device__ __forceinline__ uint32_t pack2bf(__nv_bfloat16 a, __nv_bfloat16 b) {
    __nv_bfloat162 t = __halves2bfloat162(a, b);
    return *reinterpret_cast<uint32_t*>(&t);
}
__device__ __forceinline__ void split2(float a, float b, uint32_t& hi, uint32_t& lo) {
    __nv_bfloat16 ha = __float2bfloat16(a), hb = __float2bfloat16(b);
    hi = pack2bf(ha, hb);
    lo = pack2bf(__float2bfloat16(a - __bfloat162float(ha)),
                 __float2bfloat16(b - __bfloat162float(hb)));
}

// ---------------------------------------------------------------------------
// Preprocessing kernels
// ---------------------------------------------------------------------------
__global__ __launch_bounds__(256) void split_f32(
    const float* __restrict__ src, __nv_bfloat16* __restrict__ hi,
    __nv_bfloat16* __restrict__ lo, int n)
{
    int i = (blockIdx.x * 256 + threadIdx.x) * 4;
    if (i >= n) return;
    float4 v = *(const float4*)&src[i];
    uint32_t h0, l0, h1, l1;
    split2(v.x, v.y, h0, l0);
    split2(v.z, v.w, h1, l1);
    *(uint2*)&hi[i] = make_uint2(h0, h1);
    *(uint2*)&lo[i] = make_uint2(l0, l1);
}

__global__ __launch_bounds__(256) void transpose_split(
    const float* __restrict__ w, __nv_bfloat16* __restrict__ th,
    __nv_bfloat16* __restrict__ tl, int K, int N)
{
    __shared__ float tile[32][33];
    const int nx = blockIdx.x * 32 + threadIdx.x;
    const int k0 = blockIdx.y * 32;
#pragma unroll
    for (int j = 0; j < 32; j += 8)
        tile[threadIdx.y + j][threadIdx.x] = w[(size_t)(k0 + threadIdx.y + j) * N + nx];
    __syncthreads();
    const int kx = k0 + threadIdx.x;
    const int n0 = blockIdx.x * 32;
#pragma unroll
    for (int j = 0; j < 32; j += 8) {
        float v = tile[threadIdx.x][threadIdx.y + j];
        __nv_bfloat16 h = __float2bfloat16(v);
        th[(size_t)(n0 + threadIdx.y + j) * K + kx] = h;
        tl[(size_t)(n0 + threadIdx.y + j) * K + kx] = __float2bfloat16(v - __bfloat162float(h));
    }
}

// ---------------------------------------------------------------------------
// Pipelined GEMM mainloop (128x128 CTA, BK=32, 8 warps, warp 64x32).
// 2-stage cp.async double buffer in dynamic smem.
// Layout per stage: [Ah | Al | Bh | Bl], each 128 x BKP bf16.
// ---------------------------------------------------------------------------
#define BKP 40
#define TSZ (128 * BKP)          // elems per tile
#define STG (4 * TSZ)            // elems per stage
#define GEMM_DSMEM (2 * STG * 2) // bytes = 81,920

#define ISSUE_SLAB(s_, buf_)                                                       \
    do {                                                                           \
        __nv_bfloat16* st = dbase + (buf_) * STG;                                  \
        _Pragma("unroll") for (int u = tid; u < 512; u += 256) {                   \
            const int row = u >> 2;                                                \
            const int c8 = (u & 3) * 8;                                            \
            const size_t ga = (size_t)(brow + row) * KDIM + (s_) * 32 + c8;        \
            const size_t gb = (size_t)(bcol + row) * KDIM + (s_) * 32 + c8;        \
            cp_async16(smem_u32(st + 0 * TSZ + row * BKP + c8), &Ah[ga]);          \
            cp_async16(smem_u32(st + 1 * TSZ + row * BKP + c8), &Al[ga]);          \
            cp_async16(smem_u32(st + 2 * TSZ + row * BKP + c8), &Bh[gb]);          \
            cp_async16(smem_u32(st + 3 * TSZ + row * BKP + c8), &Bl[gb]);          \
        }                                                                          \
    } while (0)

#define GEMM_MAINLOOP(Ah, Al, Bh, Bl)                                              \
    extern __shared__ __align__(16) __nv_bfloat16 dbase[];                         \
    const int tid  = threadIdx.x;                                                  \
    const int lane = tid & 31;                                                     \
    const int wid  = tid >> 5;                                                     \
    const int warp_m = (wid & 1) * 64;                                             \
    const int warp_n = (wid >> 1) * 32;                                            \
    const int brow = blockIdx.y * 128;                                             \
    const int bcol = blockIdx.x * 128;                                             \
    float acc[4][4][4];                                                            \
    _Pragma("unroll") for (int mi = 0; mi < 4; mi++)                               \
        _Pragma("unroll") for (int ni = 0; ni < 4; ni++)                           \
            _Pragma("unroll") for (int j = 0; j < 4; j++) acc[mi][ni][j] = 0.0f;   \
    const int a_row = (lane & 7) + ((lane >> 3) & 1) * 8;                          \
    const int a_kh  = (lane >> 4) * 8;                                             \
    const int b_row = lane & 7;                                                    \
    const int b_kh  = ((lane >> 3) & 1) * 8;                                       \
    ISSUE_SLAB(0, 0);                                                              \
    CP_COMMIT();                                                                   \
    for (int s = 0; s < KDIM / 32; s++) {                                          \
        if (s + 1 < KDIM / 32) { ISSUE_SLAB(s + 1, (s + 1) & 1); CP_COMMIT(); CP_WAIT(1); } \
        else { CP_WAIT(0); }                                                       \
        __syncthreads();                                                           \
        const __nv_bfloat16* cAh = dbase + (s & 1) * STG + 0 * TSZ;                \
        const __nv_bfloat16* cAl = dbase + (s & 1) * STG + 1 * TSZ;                \
        const __nv_bfloat16* cBh = dbase + (s & 1) * STG + 2 * TSZ;                \
        const __nv_bfloat16* cBl = dbase + (s & 1) * STG + 3 * TSZ;                \
        _Pragma("unroll") for (int kk = 0; kk < 2; kk++) {                         \
            const int k0 = kk * 16;                                                \
            uint32_t ah[4][4], al[4][4], bh[4][2], bl[4][2];                       \
            _Pragma("unroll") for (int mi = 0; mi < 4; mi++) {                     \
                const int r = warp_m + mi * 16 + a_row;                            \
                ldmx4(ah[mi][0], ah[mi][1], ah[mi][2], ah[mi][3],                  \
                      smem_u32(&cAh[r * BKP + k0 + a_kh]));                        \
                ldmx4(al[mi][0], al[mi][1], al[mi][2], al[mi][3],                  \
                      smem_u32(&cAl[r * BKP + k0 + a_kh]));                        \
            }                                                                      \
            _Pragma("unroll") for (int ni = 0; ni < 4; ni++) {                     \
                const int r = warp_n + ni * 8 + b_row;                             \
                ldmx2(bh[ni][0], bh[ni][1], smem_u32(&cBh[r * BKP + k0 + b_kh])); \
                ldmx2(bl[ni][0], bl[ni][1], smem_u32(&cBl[r * BKP + k0 + b_kh])); \
            }                                                                      \
            _Pragma("unroll") for (int mi = 0; mi < 4; mi++)                       \
                _Pragma("unroll") for (int ni = 0; ni < 4; ni++) {                 \
                    mma_bf16(acc[mi][ni], ah[mi], bh[ni]);                         \
                    mma_bf16(acc[mi][ni], ah[mi], bl[ni]);                         \
                    mma_bf16(acc[mi][ni], al[mi], bh[ni]);                         \
                }                                                                  \
        }                                                                          \
        __syncthreads();                                                           \
    }

// GEMM -> fp32 C + bias (out-projection)
__global__ __launch_bounds__(256) void gemm_mma_f32(
    const __nv_bfloat16* __restrict__ Ah, const __nv_bfloat16* __restrict__ Al,
    const __nv_bfloat16* __restrict__ Bh, const __nv_bfloat16* __restrict__ Bl,
    const float* __restrict__ bias, float* __restrict__ C, int N)
{
    GEMM_MAINLOOP(Ah, Al, Bh, Bl)
    const int er = brow + warp_m + (lane >> 2);
    const int ec = bcol + warp_n + (lane & 3) * 2;
#pragma unroll
    for (int mi = 0; mi < 4; mi++)
#pragma unroll
        for (int ni = 0; ni < 4; ni++) {
            const int r0 = er + mi * 16;
            const int c0 = ec + ni * 8;
            float2 v0, v1;
            v0.x = acc[mi][ni][0] + bias[c0];
            v0.y = acc[mi][ni][1] + bias[c0 + 1];
            v1.x = acc[mi][ni][2] + bias[c0];
            v1.y = acc[mi][ni][3] + bias[c0 + 1];
            *(float2*)&C[(size_t)r0 * N + c0] = v0;
            *(float2*)&C[(size_t)(r0 + 8) * N + c0] = v1;
        }
}

// GEMM -> bf16 hi/lo + bias, cols < DM (Q section) pre-scaled by 1/32 (QKV proj)
__global__ __launch_bounds__(256) void gemm_mma_qkv(
    const __nv_bfloat16* __restrict__ Ah, const __nv_bfloat16* __restrict__ Al,
    const __nv_bfloat16* __restrict__ Bh, const __nv_bfloat16* __restrict__ Bl,
    const float* __restrict__ bias,
    __nv_bfloat16* __restrict__ Ch, __nv_bfloat16* __restrict__ Cl, int N)
{
    GEMM_MAINLOOP(Ah, Al, Bh, Bl)
    const int er = brow + warp_m + (lane >> 2);
    const int ec = bcol + warp_n + (lane & 3) * 2;
#pragma unroll
    for (int mi = 0; mi < 4; mi++)
#pragma unroll
        for (int ni = 0; ni < 4; ni++) {
            const int r0 = er + mi * 16;
            const int c0 = ec + ni * 8;
            const float sc = (c0 < DM) ? 0.03125f : 1.0f;
            float v0 = (acc[mi][ni][0] + bias[c0]) * sc;
            float v1 = (acc[mi][ni][1] + bias[c0 + 1]) * sc;
            float v2 = (acc[mi][ni][2] + bias[c0]) * sc;
            float v3 = (acc[mi][ni][3] + bias[c0 + 1]) * sc;
            uint32_t h01, l01, h23, l23;
            split2(v0, v1, h01, l01);
            split2(v2, v3, h23, l23);
            *(uint32_t*)&Ch[(size_t)r0 * N + c0] = h01;
            *(uint32_t*)&Cl[(size_t)r0 * N + c0] = l01;
            *(uint32_t*)&Ch[(size_t)(r0 + 8) * N + c0] = h23;
            *(uint32_t*)&Cl[(size_t)(r0 + 8) * N + c0] = l23;
        }
}

// ---------------------------------------------------------------------------
// Flash attention, split-bf16 mma.sync (validated round 5, unchanged).
// ---------------------------------------------------------------------------
__global__ __launch_bounds__(256) void flash_attn_mma()
{
    __shared__ __align__(16) __nv_bfloat16 sKh[64][72], sKl[64][72];
    __shared__ __align__(16) __nv_bfloat16 sVh[64][72], sVl[64][72];

    const int tid = threadIdx.x, lane = tid & 31, wid = tid >> 5;
    const int qt = blockIdx.x, h = blockIdx.y, b = blockIdx.z;
    const int q0 = qt * 128;
    const size_t rowb = (size_t)b * SEQ + q0;
    const int wm = wid * 16;
    const int ra = lane >> 2;
    const int kq = (lane & 3) * 2;

    uint32_t qfh[4][4], qfl[4][4];
    {
        const size_t r0 = (rowb + wm + ra) * QKV_N + h * HD;
        const size_t r1 = (rowb + wm + ra + 8) * QKV_N + h * HD;
#pragma unroll
        for (int ks = 0; ks < 4; ks++) {
            const int c = ks * 16 + kq;
            qfh[ks][0] = *(const uint32_t*)&g_qkvh[r0 + c];
            qfh[ks][1] = *(const uint32_t*)&g_qkvh[r1 + c];
            qfh[ks][2] = *(const uint32_t*)&g_qkvh[r0 + c + 8];
            qfh[ks][3] = *(const uint32_t*)&g_qkvh[r1 + c + 8];
            qfl[ks][0] = *(const uint32_t*)&g_qkvl[r0 + c];
            qfl[ks][1] = *(const uint32_t*)&g_qkvl[r1 + c];
            qfl[ks][2] = *(const uint32_t*)&g_qkvl[r0 + c + 8];
            qfl[ks][3] = *(const uint32_t*)&g_qkvl[r1 + c + 8];
        }
    }

    float o[8][4];
#pragma unroll
    for (int dn = 0; dn < 8; dn++)
#pragma unroll
        for (int j = 0; j < 4; j++) o[dn][j] = 0.0f;
    float m_lo = -1e30f, m_hi = -1e30f, l_lo = 0.0f, l_hi = 0.0f;

    const int b_row = lane & 7;
    const int b_kh = ((lane >> 3) & 1) * 8;
    const int v_row = lane & 15;

    const int nkt = 2 * qt + 2;
    for (int kt = 0; kt < nkt; kt++) {
        const int t0 = kt * 64;
        const size_t gr = (size_t)b * SEQ + t0;
        for (int u = tid; u < 512; u += 256) {
            const int row = u >> 3;
            const int c8 = (u & 7) * 8;
            const size_t gk = (gr + row) * QKV_N + DM + h * HD + c8;
            const size_t gv = (gr + row) * QKV_N + 2 * DM + h * HD + c8;
            *(uint4*)&sKh[row][c8] = *(const uint4*)&g_qkvh[gk];
            *(uint4*)&sKl[row][c8] = *(const uint4*)&g_qkvl[gk];
            *(uint4*)&sVh[row][c8] = *(const uint4*)&g_qkvh[gv];
            *(uint4*)&sVl[row][c8] = *(const uint4*)&g_qkvl[gv];
        }
        __syncthreads();

        float s[8][4];
#pragma unroll
        for (int nt = 0; nt < 8; nt++)
#pragma unroll
            for (int j = 0; j < 4; j++) s[nt][j] = 0.0f;
#pragma unroll
        for (int nt = 0; nt < 8; nt++) {
#pragma unroll
            for (int ks = 0; ks < 4; ks++) {
                uint32_t bh[2], bl[2];
                ldmx2(bh[0], bh[1], smem_u32(&sKh[nt * 8 + b_row][ks * 16 + b_kh]));
                ldmx2(bl[0], bl[1], smem_u32(&sKl[nt * 8 + b_row][ks * 16 + b_kh]));
                mma_bf16(s[nt], qfh[ks], bh);
                mma_bf16(s[nt], qfh[ks], bl);
                mma_bf16(s[nt], qfl[ks], bh);
            }
        }

        if (t0 + 63 > q0 + wm) {
            const int row_lo = q0 + wm + ra;
            const int row_hi = row_lo + 8;
#pragma unroll
            for (int nt = 0; nt < 8; nt++) {
                const int c = t0 + nt * 8 + kq;
                if (c > row_lo) s[nt][0] = -1e30f;
                if (c + 1 > row_lo) s[nt][1] = -1e30f;
                if (c > row_hi) s[nt][2] = -1e30f;
                if (c + 1 > row_hi) s[nt][3] = -1e30f;
            }
        }

        {
            float mt0 = -1e30f, mt1 = -1e30f;
#pragma unroll
            for (int nt = 0; nt < 8; nt++) {
                mt0 = fmaxf(mt0, fmaxf(s[nt][0], s[nt][1]));
                mt1 = fmaxf(mt1, fmaxf(s[nt][2], s[nt][3]));
            }
            mt0 = fmaxf(mt0, __shfl_xor_sync(0xffffffffu, mt0, 1));
            mt0 = fmaxf(mt0, __shfl_xor_sync(0xffffffffu, mt0, 2));
            mt1 = fmaxf(mt1, __shfl_xor_sync(0xffffffffu, mt1, 1));
            mt1 = fmaxf(mt1, __shfl_xor_sync(0xffffffffu, mt1, 2));
            const float mn0 = fmaxf(m_lo, mt0);
            const float mn1 = fmaxf(m_hi, mt1);
            const float al0 = __expf(m_lo - mn0);
            const float al1 = __expf(m_hi - mn1);
            float ls0 = 0.0f, ls1 = 0.0f;
#pragma unroll
            for (int nt = 0; nt < 8; nt++) {
                s[nt][0] = __expf(s[nt][0] - mn0);
                s[nt][1] = __expf(s[nt][1] - mn0);
                s[nt][2] = __expf(s[nt][2] - mn1);
                s[nt][3] = __expf(s[nt][3] - mn1);
                ls0 += s[nt][0] + s[nt][1];
                ls1 += s[nt][2] + s[nt][3];
            }
            ls0 += __shfl_xor_sync(0xffffffffu, ls0, 1);
            ls0 += __shfl_xor_sync(0xffffffffu, ls0, 2);
            ls1 += __shfl_xor_sync(0xffffffffu, ls1, 1);
            ls1 += __shfl_xor_sync(0xffffffffu, ls1, 2);
            l_lo = l_lo * al0 + ls0;
            l_hi = l_hi * al1 + ls1;
            m_lo = mn0; m_hi = mn1;
#pragma unroll
            for (int dn = 0; dn < 8; dn++) {
                o[dn][0] *= al0; o[dn][1] *= al0;
                o[dn][2] *= al1; o[dn][3] *= al1;
            }
        }

        uint32_t ph[4][4], pl[4][4];
#pragma unroll
        for (int j = 0; j < 4; j++) {
            split2(s[2 * j][0], s[2 * j][1], ph[j][0], pl[j][0]);
            split2(s[2 * j][2], s[2 * j][3], ph[j][1], pl[j][1]);
            split2(s[2 * j + 1][0], s[2 * j + 1][1], ph[j][2], pl[j][2]);
            split2(s[2 * j + 1][2], s[2 * j + 1][3], ph[j][3], pl[j][3]);
        }

#pragma unroll
        for (int dn = 0; dn < 8; dn++) {
#pragma unroll
            for (int j = 0; j < 4; j++) {
                uint32_t vh[2], vl[2];
                ldmx2t(vh[0], vh[1], smem_u32(&sVh[j * 16 + v_row][dn * 8]));
                ldmx2t(vl[0], vl[1], smem_u32(&sVl[j * 16 + v_row][dn * 8]));
                mma_bf16(o[dn], ph[j], vh);
                mma_bf16(o[dn], ph[j], vl);
                mma_bf16(o[dn], pl[j], vh);
            }
        }
        __syncthreads();
    }

    const float il = 1.0f / l_lo;
    const float ih = 1.0f / l_hi;
    const size_t row_lo_g = rowb + wm + ra;
    const size_t row_hi_g = row_lo_g + 8;
#pragma unroll
    for (int dn = 0; dn < 8; dn++) {
        const int col = h * HD + dn * 8 + kq;
        uint32_t h01, l01, h23, l23;
        split2(o[dn][0] * il, o[dn][1] * il, h01, l01);
        split2(o[dn][2] * ih, o[dn][3] * ih, h23, l23);
        *(uint32_t*)&g_ath[row_lo_g * DM + col] = h01;
        *(uint32_t*)&g_atl[row_lo_g * DM + col] = l01;
        *(uint32_t*)&g_ath[row_hi_g * DM + col] = h23;
        *(uint32_t*)&g_atl[row_hi_g * DM + col] = l23;
    }
}

// ---------------------------------------------------------------------------
// Launcher
// ---------------------------------------------------------------------------
extern "C" void kernel_launch(void* const* d_in, const int* in_sizes, int n_in,
                              void* d_out, int out_size)
{
    const float* x     = (const float*)d_in[0];
    const float* w_qkv = (const float*)d_in[1];
    const float* b_qkv = (const float*)d_in[2];
    const float* w_out = (const float*)d_in[3];
    const float* b_out = (const float*)d_in[4];
    float* out = (float*)d_out;

    __nv_bfloat16 *xh, *xl, *wqh, *wql, *woh, *wol, *qh, *ql, *ath, *atl;
    cudaGetSymbolAddress((void**)&xh, g_x_hi);
    cudaGetSymbolAddress((void**)&xl, g_x_lo);
    cudaGetSymbolAddress((void**)&wqh, g_wq_hi);
    cudaGetSymbolAddress((void**)&wql, g_wq_lo);
    cudaGetSymbolAddress((void**)&woh, g_wo_hi);
    cudaGetSymbolAddress((void**)&wol, g_wo_lo);
    cudaGetSymbolAddress((void**)&qh, g_qkvh);
    cudaGetSymbolAddress((void**)&ql, g_qkvl);
    cudaGetSymbolAddress((void**)&ath, g_ath);
    cudaGetSymbolAddress((void**)&atl, g_atl);

    cudaFuncSetAttribute(gemm_mma_qkv, cudaFuncAttributeMaxDynamicSharedMemorySize, GEMM_DSMEM);
    cudaFuncSetAttribute(gemm_mma_f32, cudaFuncAttributeMaxDynamicSharedMemorySize, GEMM_DSMEM);

    // Preprocessing
    split_f32<<<(MROWS * KDIM / 4 + 255) / 256, 256>>>(x, xh, xl, MROWS * KDIM);
    transpose_split<<<dim3(QKV_N / 32, KDIM / 32), dim3(32, 8)>>>(w_qkv, wqh, wql, KDIM, QKV_N);
    transpose_split<<<dim3(DM / 32, KDIM / 32), dim3(32, 8)>>>(w_out, woh, wol, KDIM, DM);

    // 1) QKV projection -> bf16 hi/lo, Q section pre-scaled by 1/32
    gemm_mma_qkv<<<dim3(QKV_N / 128, MROWS / 128), 256, GEMM_DSMEM>>>(
        xh, xl, wqh, wql, b_qkv, qh, ql, QKV_N);

    // 2) Attention (split-bf16 mma) -> g_ath/g_atl
    flash_attn_mma<<<dim3(SEQ / 128, NH, BSZ), 256>>>();

    // 3) Out projection -> fp32 output
    gemm_mma_f32<<<dim3(DM / 128, MROWS / 128), 256, GEMM_DSMEM>>>(
        ath, atl, woh, wol, b_out, out, DM);
}

// round 7
// speedup vs baseline: 2.7393x; 1.0342x over previous
#include <cuda_runtime.h>
#include <cuda_bf16.h>
#include <cstdint>

// Problem constants
#define BSZ 2
#define SEQ 2048
#define DM 1024
#define NH 16
#define HD 64
#define MROWS 4096
#define QKV_N 3072
#define KDIM 1024

// ---------------------------------------------------------------------------
// Scratch (__device__ globals; allocation-free rule)
// ---------------------------------------------------------------------------
__device__ __align__(16) __nv_bfloat16 g_x_hi[MROWS * KDIM];
__device__ __align__(16) __nv_bfloat16 g_x_lo[MROWS * KDIM];
__device__ __align__(16) __nv_bfloat16 g_wq_hi[QKV_N * KDIM];
__device__ __align__(16) __nv_bfloat16 g_wq_lo[QKV_N * KDIM];
__device__ __align__(16) __nv_bfloat16 g_wo_hi[DM * KDIM];
__device__ __align__(16) __nv_bfloat16 g_wo_lo[DM * KDIM];
__device__ __align__(16) __nv_bfloat16 g_qkvh[MROWS * QKV_N];
__device__ __align__(16) __nv_bfloat16 g_qkvl[MROWS * QKV_N];
__device__ __align__(16) __nv_bfloat16 g_ath[MROWS * DM];
__device__ __align__(16) __nv_bfloat16 g_atl[MROWS * DM];

// ---------------------------------------------------------------------------
// PTX helpers
// ---------------------------------------------------------------------------
__device__ __forceinline__ uint32_t smem_u32(const void* p) {
    uint32_t a;
    asm("{ .reg .u64 t; cvta.to.shared.u64 t, %1; cvt.u32.u64 %0, t; }" : "=r"(a) : "l"(p));
    return a;
}
__device__ __forceinline__ void ldmx4(uint32_t& r0, uint32_t& r1, uint32_t& r2,
                                      uint32_t& r3, uint32_t addr) {
    asm volatile("ldmatrix.sync.aligned.m8n8.x4.shared.b16 {%0,%1,%2,%3}, [%4];"
                 : "=r"(r0), "=r"(r1), "=r"(r2), "=r"(r3) : "r"(addr));
}
__device__ __forceinline__ void ldmx4t(uint32_t& r0, uint32_t& r1, uint32_t& r2,
                                       uint32_t& r3, uint32_t addr) {
    asm volatile("ldmatrix.sync.aligned.m8n8.x4.trans.shared.b16 {%0,%1,%2,%3}, [%4];"
                 : "=r"(r0), "=r"(r1), "=r"(r2), "=r"(r3) : "r"(addr));
}
__device__ __forceinline__ void mma_bf16(float* c, const uint32_t* a, const uint32_t* b) {
    asm volatile(
        "mma.sync.aligned.m16n8k16.row.col.f32.bf16.bf16.f32 "
        "{%0,%1,%2,%3}, {%4,%5,%6,%7}, {%8,%9}, {%0,%1,%2,%3};"
        : "+f"(c[0]), "+f"(c[1]), "+f"(c[2]), "+f"(c[3])
        : "r"(a[0]), "r"(a[1]), "r"(a[2]), "r"(a[3]), "r"(b[0]), "r"(b[1]));
}
__device__ __forceinline__ void cp_async16(uint32_t saddr, const void* g) {
    asm volatile("cp.async.cg.shared.global [%0], [%1], 16;" :: "r"(saddr), "l"(g));
}
#define CP_COMMIT() asm volatile("cp.async.commit_group;" ::: "memory")
#define CP_WAIT(n)  asm volatile("cp.async.wait_group %0;" :: "n"(n) : "memory")

__device__ __forceinline__ uint32_t pack2bf(__nv_bfloat16 a, __nv_bfloat16 b) {
    __nv_bfloat162 t = __halves2bfloat162(a, b);
    return *reinterpret_cast<uint32_t*>(&t);
}
__device__ __forceinline__ void split2(float a, float b, uint32_t& hi, uint32_t& lo) {
    __nv_bfloat16 ha = __float2bfloat16(a), hb = __float2bfloat16(b);
    hi = pack2bf(ha, hb);
    lo = pack2bf(__float2bfloat16(a - __bfloat162float(ha)),
                 __float2bfloat16(b - __bfloat162float(hb)));
}

// ---------------------------------------------------------------------------
// Preprocessing kernels
// ---------------------------------------------------------------------------
__global__ __launch_bounds__(256) void split_f32(
    const float* __restrict__ src, __nv_bfloat16* __restrict__ hi,
    __nv_bfloat16* __restrict__ lo, int n)
{
    int i = (blockIdx.x * 256 + threadIdx.x) * 4;
    if (i >= n) return;
    float4 v = *(const float4*)&src[i];
    uint32_t h0, l0, h1, l1;
    split2(v.x, v.y, h0, l0);
    split2(v.z, v.w, h1, l1);
    *(uint2*)&hi[i] = make_uint2(h0, h1);
    *(uint2*)&lo[i] = make_uint2(l0, l1);
}

__global__ __launch_bounds__(256) void transpose_split(
    const float* __restrict__ w, __nv_bfloat16* __restrict__ th,
    __nv_bfloat16* __restrict__ tl, int K, int N)
{
    __shared__ float tile[32][33];
    const int nx = blockIdx.x * 32 + threadIdx.x;
    const int k0 = blockIdx.y * 32;
#pragma unroll
    for (int j = 0; j < 32; j += 8)
        tile[threadIdx.y + j][threadIdx.x] = w[(size_t)(k0 + threadIdx.y + j) * N + nx];
    __syncthreads();
    const int kx = k0 + threadIdx.x;
    const int n0 = blockIdx.x * 32;
#pragma unroll
    for (int j = 0; j < 32; j += 8) {
        float v = tile[threadIdx.x][threadIdx.y + j];
        __nv_bfloat16 h = __float2bfloat16(v);
        th[(size_t)(n0 + threadIdx.y + j) * K + kx] = h;
        tl[(size_t)(n0 + threadIdx.y + j) * K + kx] = __float2bfloat16(v - __bfloat162float(h));
    }
}

// ---------------------------------------------------------------------------
// Pipelined GEMM mainloop (128x128 CTA, BK=32, 8 warps, warp 64x32).
// 2-stage cp.async double buffer; B-frags fetched pairwise via ldmatrix.x4.
// ---------------------------------------------------------------------------
#define BKP 40
#define TSZ (128 * BKP)
#define STG (4 * TSZ)
#define GEMM_DSMEM (2 * STG * 2)

#define ISSUE_SLAB(s_, buf_)                                                       \
    do {                                                                           \
        __nv_bfloat16* st = dbase + (buf_) * STG;                                  \
        _Pragma("unroll") for (int u = tid; u < 512; u += 256) {                   \
            const int row = u >> 2;                                                \
            const int c8 = (u & 3) * 8;                                            \
            const size_t ga = (size_t)(brow + row) * KDIM + (s_) * 32 + c8;        \
            const size_t gb = (size_t)(bcol + row) * KDIM + (s_) * 32 + c8;        \
            cp_async16(smem_u32(st + 0 * TSZ + row * BKP + c8), &Ah[ga]);          \
            cp_async16(smem_u32(st + 1 * TSZ + row * BKP + c8), &Al[ga]);          \
            cp_async16(smem_u32(st + 2 * TSZ + row * BKP + c8), &Bh[gb]);          \
            cp_async16(smem_u32(st + 3 * TSZ + row * BKP + c8), &Bl[gb]);          \
        }                                                                          \
    } while (0)

#define GEMM_MAINLOOP(Ah, Al, Bh, Bl)                                              \
    extern __shared__ __align__(16) __nv_bfloat16 dbase[];                         \
    const int tid  = threadIdx.x;                                                  \
    const int lane = tid & 31;                                                     \
    const int wid  = tid >> 5;                                                     \
    const int warp_m = (wid & 1) * 64;                                             \
    const int warp_n = (wid >> 1) * 32;                                            \
    const int brow = blockIdx.y * 128;                                             \
    const int bcol = blockIdx.x * 128;                                             \
    float acc[4][4][4];                                                            \
    _Pragma("unroll") for (int mi = 0; mi < 4; mi++)                               \
        _Pragma("unroll") for (int ni = 0; ni < 4; ni++)                           \
            _Pragma("unroll") for (int j = 0; j < 4; j++) acc[mi][ni][j] = 0.0f;   \
    const int a_row = (lane & 7) + ((lane >> 3) & 1) * 8;                          \
    const int a_kh  = (lane >> 4) * 8;                                             \
    const int bx4_row = (lane & 7) + ((lane >> 4) & 1) * 8;                        \
    const int b_kh  = ((lane >> 3) & 1) * 8;                                       \
    ISSUE_SLAB(0, 0);                                                              \
    CP_COMMIT();                                                                   \
    for (int s = 0; s < KDIM / 32; s++) {                                          \
        if (s + 1 < KDIM / 32) { ISSUE_SLAB(s + 1, (s + 1) & 1); CP_COMMIT(); CP_WAIT(1); } \
        else { CP_WAIT(0); }                                                       \
        __syncthreads();                                                           \
        const __nv_bfloat16* cAh = dbase + (s & 1) * STG + 0 * TSZ;                \
        const __nv_bfloat16* cAl = dbase + (s & 1) * STG + 1 * TSZ;                \
        const __nv_bfloat16* cBh = dbase + (s & 1) * STG + 2 * TSZ;                \
        const __nv_bfloat16* cBl = dbase + (s & 1) * STG + 3 * TSZ;                \
        _Pragma("unroll") for (int kk = 0; kk < 2; kk++) {                         \
            const int k0 = kk * 16;                                                \
            uint32_t ah[4][4], al[4][4], bh[4][2], bl[4][2];                       \
            _Pragma("unroll") for (int mi = 0; mi < 4; mi++) {                     \
                const int r = warp_m + mi * 16 + a_row;                            \
                ldmx4(ah[mi][0], ah[mi][1], ah[mi][2], ah[mi][3],                  \
                      smem_u32(&cAh[r * BKP + k0 + a_kh]));                        \
                ldmx4(al[mi][0], al[mi][1], al[mi][2], al[mi][3],                  \
                      smem_u32(&cAl[r * BKP + k0 + a_kh]));                        \
            }                                                                      \
            _Pragma("unroll") for (int pr = 0; pr < 2; pr++) {                     \
                const int r = warp_n + pr * 16 + bx4_row;                          \
                ldmx4(bh[2 * pr][0], bh[2 * pr][1], bh[2 * pr + 1][0],             \
                      bh[2 * pr + 1][1], smem_u32(&cBh[r * BKP + k0 + b_kh]));     \
                ldmx4(bl[2 * pr][0], bl[2 * pr][1], bl[2 * pr + 1][0],             \
                      bl[2 * pr + 1][1], smem_u32(&cBl[r * BKP + k0 + b_kh]));     \
            }                                                                      \
            _Pragma("unroll") for (int mi = 0; mi < 4; mi++)                       \
                _Pragma("unroll") for (int ni = 0; ni < 4; ni++) {                 \
                    mma_bf16(acc[mi][ni], ah[mi], bh[ni]);                         \
                    mma_bf16(acc[mi][ni], ah[mi], bl[ni]);                         \
                    mma_bf16(acc[mi][ni], al[mi], bh[ni]);                         \
                }                                                                  \
        }                                                                          \
        __syncthreads();                                                           \
    }

__global__ __launch_bounds__(256) void gemm_mma_f32(
    const __nv_bfloat16* __restrict__ Ah, const __nv_bfloat16* __restrict__ Al,
    const __nv_bfloat16* __restrict__ Bh, const __nv_bfloat16* __restrict__ Bl,
    const float* __restrict__ bias, float* __restrict__ C, int N)
{
    GEMM_MAINLOOP(Ah, Al, Bh, Bl)
    const int er = brow + warp_m + (lane >> 2);
    const int ec = bcol + warp_n + (lane & 3) * 2;
#pragma unroll
    for (int mi = 0; mi < 4; mi++)
#pragma unroll
        for (int ni = 0; ni < 4; ni++) {
            const int r0 = er + mi * 16;
            const int c0 = ec + ni * 8;
            float2 v0, v1;
            v0.x = acc[mi][ni][0] + bias[c0];
            v0.y = acc[mi][ni][1] + bias[c0 + 1];
            v1.x = acc[mi][ni][2] + bias[c0];
            v1.y = acc[mi][ni][3] + bias[c0 + 1];
            *(float2*)&C[(size_t)r0 * N + c0] = v0;
            *(float2*)&C[(size_t)(r0 + 8) * N + c0] = v1;
        }
}

__global__ __launch_bounds__(256) void gemm_mma_qkv(
    const __nv_bfloat16* __restrict__ Ah, const __nv_bfloat16* __restrict__ Al,
    const __nv_bfloat16* __restrict__ Bh, const __nv_bfloat16* __restrict__ Bl,
    const float* __restrict__ bias,
    __nv_bfloat16* __restrict__ Ch, __nv_bfloat16* __restrict__ Cl, int N)
{
    GEMM_MAINLOOP(Ah, Al, Bh, Bl)
    const int er = brow + warp_m + (lane >> 2);
    const int ec = bcol + warp_n + (lane & 3) * 2;
#pragma unroll
    for (int mi = 0; mi < 4; mi++)
#pragma unroll
        for (int ni = 0; ni < 4; ni++) {
            const int r0 = er + mi * 16;
            const int c0 = ec + ni * 8;
            const float sc = (c0 < DM) ? 0.03125f : 1.0f;
            float v0 = (acc[mi][ni][0] + bias[c0]) * sc;
            float v1 = (acc[mi][ni][1] + bias[c0 + 1]) * sc;
            float v2 = (acc[mi][ni][2] + bias[c0]) * sc;
            float v3 = (acc[mi][ni][3] + bias[c0 + 1]) * sc;
            uint32_t h01, l01, h23, l23;
            split2(v0, v1, h01, l01);
            split2(v2, v3, h23, l23);
            *(uint32_t*)&Ch[(size_t)r0 * N + c0] = h01;
            *(uint32_t*)&Cl[(size_t)r0 * N + c0] = l01;
            *(uint32_t*)&Ch[(size_t)(r0 + 8) * N + c0] = h23;
            *(uint32_t*)&Cl[(size_t)(r0 + 8) * N + c0] = l23;
        }
}

// ---------------------------------------------------------------------------
// Flash attention, split-bf16 mma.sync + cp.async double-buffered K/V.
// qt reversed so longest (diagonal-heavy) CTAs launch first.
// ---------------------------------------------------------------------------
#define AT_TILE (64 * 72)
#define AT_STG (4 * AT_TILE)
#define ATTN_DSMEM (2 * AT_STG * 2)   // 73,728 B

#define ISSUE_KV(kt_, buf_)                                                        \
    do {                                                                           \
        __nv_bfloat16* st = abase + (buf_) * AT_STG;                               \
        const size_t gr = (size_t)b * SEQ + (kt_) * 64;                            \
        _Pragma("unroll") for (int u = tid; u < 512; u += 256) {                   \
            const int row = u >> 3;                                                \
            const int c8 = (u & 7) * 8;                                            \
            const size_t gk = (gr + row) * QKV_N + DM + h * HD + c8;               \
            cp_async16(smem_u32(st + 0 * AT_TILE + row * 72 + c8), &g_qkvh[gk]);   \
            cp_async16(smem_u32(st + 1 * AT_TILE + row * 72 + c8), &g_qkvl[gk]);   \
            cp_async16(smem_u32(st + 2 * AT_TILE + row * 72 + c8), &g_qkvh[gk + DM]); \
            cp_async16(smem_u32(st + 3 * AT_TILE + row * 72 + c8), &g_qkvl[gk + DM]); \
        }                                                                          \
    } while (0)

__global__ __launch_bounds__(256) void flash_attn_mma()
{
    extern __shared__ __align__(16) __nv_bfloat16 abase[];

    const int tid = threadIdx.x, lane = tid & 31, wid = tid >> 5;
    const int qt = gridDim.x - 1 - blockIdx.x;   // longest CTAs first
    const int h = blockIdx.y, b = blockIdx.z;
    const int q0 = qt * 128;
    const size_t rowb = (size_t)b * SEQ + q0;
    const int wm = wid * 16;
    const int ra = lane >> 2;
    const int kq = (lane & 3) * 2;

    // Q a-frags from global (fragment layout addressing)
    uint32_t qfh[4][4], qfl[4][4];
    {
        const size_t r0 = (rowb + wm + ra) * QKV_N + h * HD;
        const size_t r1 = (rowb + wm + ra + 8) * QKV_N + h * HD;
#pragma unroll
        for (int ks = 0; ks < 4; ks++) {
            const int c = ks * 16 + kq;
            qfh[ks][0] = *(const uint32_t*)&g_qkvh[r0 + c];
            qfh[ks][1] = *(const uint32_t*)&g_qkvh[r1 + c];
            qfh[ks][2] = *(const uint32_t*)&g_qkvh[r0 + c + 8];
            qfh[ks][3] = *(const uint32_t*)&g_qkvh[r1 + c + 8];
            qfl[ks][0] = *(const uint32_t*)&g_qkvl[r0 + c];
            qfl[ks][1] = *(const uint32_t*)&g_qkvl[r1 + c];
            qfl[ks][2] = *(const uint32_t*)&g_qkvl[r0 + c + 8];
            qfl[ks][3] = *(const uint32_t*)&g_qkvl[r1 + c + 8];
        }
    }

    float o[8][4];
#pragma unroll
    for (int dn = 0; dn < 8; dn++)
#pragma unroll
        for (int j = 0; j < 4; j++) o[dn][j] = 0.0f;
    float m_lo = -1e30f, m_hi = -1e30f, l_lo = 0.0f, l_hi = 0.0f;

    const int bx4_row = (lane & 7) + ((lane >> 4) & 1) * 8;
    const int b_kh = ((lane >> 3) & 1) * 8;
    const int v_row = lane & 15;
    const int v_ch = ((lane >> 4) & 1) * 8;

    const int nkt = 2 * qt + 2;
    ISSUE_KV(0, 0);
    CP_COMMIT();

    for (int kt = 0; kt < nkt; kt++) {
        if (kt + 1 < nkt) { ISSUE_KV(kt + 1, (kt + 1) & 1); CP_COMMIT(); CP_WAIT(1); }
        else { CP_WAIT(0); }
        __syncthreads();
        const __nv_bfloat16* sKh = abase + (kt & 1) * AT_STG + 0 * AT_TILE;
        const __nv_bfloat16* sKl = abase + (kt & 1) * AT_STG + 1 * AT_TILE;
        const __nv_bfloat16* sVh = abase + (kt & 1) * AT_STG + 2 * AT_TILE;
        const __nv_bfloat16* sVl = abase + (kt & 1) * AT_STG + 3 * AT_TILE;
        const int t0 = kt * 64;

        // --- S = Q K^T (3-term split), K-frags pairwise via ldmatrix.x4 ---
        float s[8][4];
#pragma unroll
        for (int nt = 0; nt < 8; nt++)
#pragma unroll
            for (int j = 0; j < 4; j++) s[nt][j] = 0.0f;
#pragma unroll
        for (int pr = 0; pr < 4; pr++) {
            const int r = pr * 16 + bx4_row;
#pragma unroll
            for (int ks = 0; ks < 4; ks++) {
                uint32_t kh0[2], kh1[2], kl0[2], kl1[2];
                ldmx4(kh0[0], kh0[1], kh1[0], kh1[1],
                      smem_u32(&sKh[r * 72 + ks * 16 + b_kh]));
                ldmx4(kl0[0], kl0[1], kl1[0], kl1[1],
                      smem_u32(&sKl[r * 72 + ks * 16 + b_kh]));
                mma_bf16(s[2 * pr], qfh[ks], kh0);
                mma_bf16(s[2 * pr], qfh[ks], kl0);
                mma_bf16(s[2 * pr], qfl[ks], kh0);
                mma_bf16(s[2 * pr + 1], qfh[ks], kh1);
                mma_bf16(s[2 * pr + 1], qfh[ks], kl1);
                mma_bf16(s[2 * pr + 1], qfl[ks], kh1);
            }
        }

        // --- Causal mask ---
        if (t0 + 63 > q0 + wm) {
            const int row_lo = q0 + wm + ra;
            const int row_hi = row_lo + 8;
#pragma unroll
            for (int nt = 0; nt < 8; nt++) {
                const int c = t0 + nt * 8 + kq;
                if (c > row_lo) s[nt][0] = -1e30f;
                if (c + 1 > row_lo) s[nt][1] = -1e30f;
                if (c > row_hi) s[nt][2] = -1e30f;
                if (c + 1 > row_hi) s[nt][3] = -1e30f;
            }
        }

        // --- Online softmax ---
        {
            float mt0 = -1e30f, mt1 = -1e30f;
#pragma unroll
            for (int nt = 0; nt < 8; nt++) {
                mt0 = fmaxf(mt0, fmaxf(s[nt][0], s[nt][1]));
                mt1 = fmaxf(mt1, fmaxf(s[nt][2], s[nt][3]));
            }
            mt0 = fmaxf(mt0, __shfl_xor_sync(0xffffffffu, mt0, 1));
            mt0 = fmaxf(mt0, __shfl_xor_sync(0xffffffffu, mt0, 2));
            mt1 = fmaxf(mt1, __shfl_xor_sync(0xffffffffu, mt1, 1));
            mt1 = fmaxf(mt1, __shfl_xor_sync(0xffffffffu, mt1, 2));
            const float mn0 = fmaxf(m_lo, mt0);
            const float mn1 = fmaxf(m_hi, mt1);
            const float al0 = __expf(m_lo - mn0);
            const float al1 = __expf(m_hi - mn1);
            float ls0 = 0.0f, ls1 = 0.0f;
#pragma unroll
            for (int nt = 0; nt < 8; nt++) {
                s[nt][0] = __expf(s[nt][0] - mn0);
                s[nt][1] = __expf(s[nt][1] - mn0);
                s[nt][2] = __expf(s[nt][2] - mn1);
                s[nt][3] = __expf(s[nt][3] - mn1);
                ls0 += s[nt][0] + s[nt][1];
                ls1 += s[nt][2] + s[nt][3];
            }
            ls0 += __shfl_xor_sync(0xffffffffu, ls0, 1);
            ls0 += __shfl_xor_sync(0xffffffffu, ls0, 2);
            ls1 += __shfl_xor_sync(0xffffffffu, ls1, 1);
            ls1 += __shfl_xor_sync(0xffffffffu, ls1, 2);
            l_lo = l_lo * al0 + ls0;
            l_hi = l_hi * al1 + ls1;
            m_lo = mn0; m_hi = mn1;
#pragma unroll
            for (int dn = 0; dn < 8; dn++) {
                o[dn][0] *= al0; o[dn][1] *= al0;
                o[dn][2] *= al1; o[dn][3] *= al1;
            }
        }

        // --- P repack (c-frag -> a-frag) with hi/lo split ---
        uint32_t ph[4][4], pl[4][4];
#pragma unroll
        for (int j = 0; j < 4; j++) {
            split2(s[2 * j][0], s[2 * j][1], ph[j][0], pl[j][0]);
            split2(s[2 * j][2], s[2 * j][3], ph[j][1], pl[j][1]);
            split2(s[2 * j + 1][0], s[2 * j + 1][1], ph[j][2], pl[j][2]);
            split2(s[2 * j + 1][2], s[2 * j + 1][3], ph[j][3], pl[j][3]);
        }

        // --- O += P V (3-term split), V-frags pairwise via ldmatrix.x4.trans ---
#pragma unroll
        for (int dp = 0; dp < 4; dp++) {
#pragma unroll
            for (int j = 0; j < 4; j++) {
                uint32_t vh0[2], vh1[2], vl0[2], vl1[2];
                ldmx4t(vh0[0], vh0[1], vh1[0], vh1[1],
                       smem_u32(&sVh[(j * 16 + v_row) * 72 + dp * 16 + v_ch]));
                ldmx4t(vl0[0], vl0[1], vl1[0], vl1[1],
                       smem_u32(&sVl[(j * 16 + v_row) * 72 + dp * 16 + v_ch]));
                mma_bf16(o[2 * dp], ph[j], vh0);
                mma_bf16(o[2 * dp], ph[j], vl0);
                mma_bf16(o[2 * dp], pl[j], vh0);
                mma_bf16(o[2 * dp + 1], ph[j], vh1);
                mma_bf16(o[2 * dp + 1], ph[j], vl1);
                mma_bf16(o[2 * dp + 1], pl[j], vh1);
            }
        }
        __syncthreads();
    }

    // --- Finalize ---
    const float il = 1.0f / l_lo;
    const float ih = 1.0f / l_hi;
    const size_t row_lo_g = rowb + wm + ra;
    const size_t row_hi_g = row_lo_g + 8;
#pragma unroll
    for (int dn = 0; dn < 8; dn++) {
        const int col = h * HD + dn * 8 + kq;
        uint32_t h01, l01, h23, l23;
        split2(o[dn][0] * il, o[dn][1] * il, h01, l01);
        split2(o[dn][2] * ih, o[dn][3] * ih, h23, l23);
        *(uint32_t*)&g_ath[row_lo_g * DM + col] = h01;
        *(uint32_t*)&g_atl[row_lo_g * DM + col] = l01;
        *(uint32_t*)&g_ath[row_hi_g * DM + col] = h23;
        *(uint32_t*)&g_atl[row_hi_g * DM + col] = l23;
    }
}

// ---------------------------------------------------------------------------
// Launcher
// ---------------------------------------------------------------------------
extern "C" void kernel_launch(void* const* d_in, const int* in_sizes, int n_in,
                              void* d_out, int out_size)
{
    const float* x     = (const float*)d_in[0];
    const float* w_qkv = (const float*)d_in[1];
    const float* b_qkv = (const float*)d_in[2];
    const float* w_out = (const float*)d_in[3];
    const float* b_out = (const float*)d_in[4];
    float* out = (float*)d_out;

    __nv_bfloat16 *xh, *xl, *wqh, *wql, *woh, *wol, *qh, *ql, *ath, *atl;
    cudaGetSymbolAddress((void**)&xh, g_x_hi);
    cudaGetSymbolAddress((void**)&xl, g_x_lo);
    cudaGetSymbolAddress((void**)&wqh, g_wq_hi);
    cudaGetSymbolAddress((void**)&wql, g_wq_lo);
    cudaGetSymbolAddress((void**)&woh, g_wo_hi);
    cudaGetSymbolAddress((void**)&wol, g_wo_lo);
    cudaGetSymbolAddress((void**)&qh, g_qkvh);
    cudaGetSymbolAddress((void**)&ql, g_qkvl);
    cudaGetSymbolAddress((void**)&ath, g_ath);
    cudaGetSymbolAddress((void**)&atl, g_atl);

    cudaFuncSetAttribute(gemm_mma_qkv, cudaFuncAttributeMaxDynamicSharedMemorySize, GEMM_DSMEM);
    cudaFuncSetAttribute(gemm_mma_f32, cudaFuncAttributeMaxDynamicSharedMemorySize, GEMM_DSMEM);
    cudaFuncSetAttribute(flash_attn_mma, cudaFuncAttributeMaxDynamicSharedMemorySize, ATTN_DSMEM);

    // Preprocessing
    split_f32<<<(MROWS * KDIM / 4 + 255) / 256, 256>>>(x, xh, xl, MROWS * KDIM);
    transpose_split<<<dim3(QKV_N / 32, KDIM / 32), dim3(32, 8)>>>(w_qkv, wqh, wql, KDIM, QKV_N);
    transpose_split<<<dim3(DM / 32, KDIM / 32), dim3(32, 8)>>>(w_out, woh, wol, KDIM, DM);

    // 1) QKV projection -> bf16 hi/lo, Q section pre-scaled by 1/32
    gemm_mma_qkv<<<dim3(QKV_N / 128, MROWS / 128), 256, GEMM_DSMEM>>>(
        xh, xl, wqh, wql, b_qkv, qh, ql, QKV_N);

    // 2) Attention (split-bf16 mma, pipelined) -> g_ath/g_atl
    flash_attn_mma<<<dim3(SEQ / 128, NH, BSZ), 256, ATTN_DSMEM>>>();

    // 3) Out projection -> fp32 output
    gemm_mma_f32<<<dim3(DM / 128, MROWS / 128), 256, GEMM_DSMEM>>>(
        ath, atl, woh, wol, b_out, out, DM);
}

// round 9
// speedup vs baseline: 3.9561x; 1.4442x over previous
#include <cuda_runtime.h>
#include <cuda_fp16.h>
#include <cstdint>

// Problem constants
#define BSZ 2
#define SEQ 2048
#define DM 1024
#define NH 16
#define HD 64
#define MROWS 4096
#define QKV_N 3072
#define KDIM 1024

// ---------------------------------------------------------------------------
// Scratch (__device__ globals; allocation-free rule). All fp16 now.
// ---------------------------------------------------------------------------
__device__ __align__(16) __half g_xh[MROWS * KDIM];        // x single fp16
__device__ __align__(16) __half g_wqh[QKV_N * KDIM];       // w_qkv^T hi
__device__ __align__(16) __half g_wql[QKV_N * KDIM];       // w_qkv^T lo
__device__ __align__(16) __half g_woh[DM * KDIM];          // w_out^T hi
__device__ __align__(16) __half g_wol[DM * KDIM];          // w_out^T lo
__device__ __align__(16) __half g_qkvh[MROWS * QKV_N];     // Q(scaled,single) K(single) V(hi)
__device__ __align__(16) __half g_vlo[MROWS * DM];         // V lo
__device__ __align__(16) __half g_ath[MROWS * DM];         // attn out hi
__device__ __align__(16) __half g_atl[MROWS * DM];         // attn out lo

// ---------------------------------------------------------------------------
// PTX helpers
// ---------------------------------------------------------------------------
__device__ __forceinline__ uint32_t smem_u32(const void* p) {
    uint32_t a;
    asm("{ .reg .u64 t; cvta.to.shared.u64 t, %1; cvt.u32.u64 %0, t; }" : "=r"(a) : "l"(p));
    return a;
}
__device__ __forceinline__ void ldmx4(uint32_t& r0, uint32_t& r1, uint32_t& r2,
                                      uint32_t& r3, uint32_t addr) {
    asm volatile("ldmatrix.sync.aligned.m8n8.x4.shared.b16 {%0,%1,%2,%3}, [%4];"
                 : "=r"(r0), "=r"(r1), "=r"(r2), "=r"(r3) : "r"(addr));
}
__device__ __forceinline__ void ldmx4t(uint32_t& r0, uint32_t& r1, uint32_t& r2,
                                       uint32_t& r3, uint32_t addr) {
    asm volatile("ldmatrix.sync.aligned.m8n8.x4.trans.shared.b16 {%0,%1,%2,%3}, [%4];"
                 : "=r"(r0), "=r"(r1), "=r"(r2), "=r"(r3) : "r"(addr));
}
__device__ __forceinline__ void mma_f16(float* c, const uint32_t* a, const uint32_t* b) {
    asm volatile(
        "mma.sync.aligned.m16n8k16.row.col.f32.f16.f16.f32 "
        "{%0,%1,%2,%3}, {%4,%5,%6,%7}, {%8,%9}, {%0,%1,%2,%3};"
        : "+f"(c[0]), "+f"(c[1]), "+f"(c[2]), "+f"(c[3])
        : "r"(a[0]), "r"(a[1]), "r"(a[2]), "r"(a[3]), "r"(b[0]), "r"(b[1]));
}
__device__ __forceinline__ void cp_async16(uint32_t saddr, const void* g) {
    asm volatile("cp.async.cg.shared.global [%0], [%1], 16;" :: "r"(saddr), "l"(g));
}
#define CP_COMMIT() asm volatile("cp.async.commit_group;" ::: "memory")
#define CP_WAIT(n)  asm volatile("cp.async.wait_group %0;" :: "n"(n) : "memory")

__device__ __forceinline__ uint32_t pack2h(__half a, __half b) {
    __half2 t = __halves2half2(a, b);
    return *reinterpret_cast<uint32_t*>(&t);
}
// Split two fp32 into packed fp16 hi/lo pairs
__device__ __forceinline__ void split2h(float a, float b, uint32_t& hi, uint32_t& lo) {
    __half ha = __float2half_rn(a), hb = __float2half_rn(b);
    hi = pack2h(ha, hb);
    lo = pack2h(__float2half_rn(a - __half2float(ha)),
                __float2half_rn(b - __half2float(hb)));
}

// ---------------------------------------------------------------------------
// Preprocessing
// ---------------------------------------------------------------------------
__global__ __launch_bounds__(256) void to_f16(
    const float* __restrict__ src, __half* __restrict__ dst, int n)
{
    int i = (blockIdx.x * 256 + threadIdx.x) * 4;
    if (i >= n) return;
    float4 v = *(const float4*)&src[i];
    uint2 o;
    o.x = pack2h(__float2half_rn(v.x), __float2half_rn(v.y));
    o.y = pack2h(__float2half_rn(v.z), __float2half_rn(v.w));
    *(uint2*)&dst[i] = o;
}

__global__ __launch_bounds__(256) void transpose_split(
    const float* __restrict__ w, __half* __restrict__ th,
    __half* __restrict__ tl, int K, int N)
{
    __shared__ float tile[32][33];
    const int nx = blockIdx.x * 32 + threadIdx.x;
    const int k0 = blockIdx.y * 32;
#pragma unroll
    for (int j = 0; j < 32; j += 8)
        tile[threadIdx.y + j][threadIdx.x] = w[(size_t)(k0 + threadIdx.y + j) * N + nx];
    __syncthreads();
    const int kx = k0 + threadIdx.x;
    const int n0 = blockIdx.x * 32;
#pragma unroll
    for (int j = 0; j < 32; j += 8) {
        float v = tile[threadIdx.x][threadIdx.y + j];
        __half hh = __float2half_rn(v);
        th[(size_t)(n0 + threadIdx.y + j) * K + kx] = hh;
        tl[(size_t)(n0 + threadIdx.y + j) * K + kx] = __float2half_rn(v - __half2float(hh));
    }
}

// ---------------------------------------------------------------------------
// QKV GEMM: A single fp16 [M,K], B 2-term fp16 [N,K]. 2 MMAs per cell-step.
// 128x128 CTA, BK=32, 8 warps (warp 64x32), 2-stage cp.async (3 tiles/stage).
// Epilogue: col<DM -> Q single scaled 1/32; <2DM -> K single; else V hi + lo.
// ---------------------------------------------------------------------------
#define BKP 40
#define TSZ (128 * BKP)
#define Q_STG (3 * TSZ)
#define QKV_DSMEM (2 * Q_STG * 2)   // 61,440 B

__global__ __launch_bounds__(256) void gemm_qkv(
    const __half* __restrict__ A, const __half* __restrict__ Bh,
    const __half* __restrict__ Bl, const float* __restrict__ bias)
{
    extern __shared__ __align__(16) __half qbase[];
    const int tid  = threadIdx.x;
    const int lane = tid & 31;
    const int wid  = tid >> 5;
    const int warp_m = (wid & 1) * 64;
    const int warp_n = (wid >> 1) * 32;
    const int brow = blockIdx.y * 128;
    const int bcol = blockIdx.x * 128;

    float acc[4][4][4];
#pragma unroll
    for (int mi = 0; mi < 4; mi++)
#pragma unroll
        for (int ni = 0; ni < 4; ni++)
#pragma unroll
            for (int j = 0; j < 4; j++) acc[mi][ni][j] = 0.0f;

    const int a_row = (lane & 7) + ((lane >> 3) & 1) * 8;
    const int a_kh  = (lane >> 4) * 8;
    const int bx4_row = (lane & 7) + ((lane >> 4) & 1) * 8;
    const int b_kh  = ((lane >> 3) & 1) * 8;

#define Q_ISSUE(s_, buf_)                                                        \
    do {                                                                         \
        __half* st = qbase + (buf_) * Q_STG;                                     \
        _Pragma("unroll") for (int u = tid; u < 512; u += 256) {                 \
            const int row = u >> 2;                                              \
            const int c8 = (u & 3) * 8;                                          \
            const size_t ga = (size_t)(brow + row) * KDIM + (s_) * 32 + c8;      \
            const size_t gb = (size_t)(bcol + row) * KDIM + (s_) * 32 + c8;      \
            cp_async16(smem_u32(st + 0 * TSZ + row * BKP + c8), &A[ga]);         \
            cp_async16(smem_u32(st + 1 * TSZ + row * BKP + c8), &Bh[gb]);        \
            cp_async16(smem_u32(st + 2 * TSZ + row * BKP + c8), &Bl[gb]);        \
        }                                                                        \
    } while (0)

    Q_ISSUE(0, 0);
    CP_COMMIT();
    for (int s = 0; s < KDIM / 32; s++) {
        if (s + 1 < KDIM / 32) { Q_ISSUE(s + 1, (s + 1) & 1); CP_COMMIT(); CP_WAIT(1); }
        else { CP_WAIT(0); }
        __syncthreads();
        const __half* cA  = qbase + (s & 1) * Q_STG + 0 * TSZ;
        const __half* cBh = qbase + (s & 1) * Q_STG + 1 * TSZ;
        const __half* cBl = qbase + (s & 1) * Q_STG + 2 * TSZ;
#pragma unroll
        for (int kk = 0; kk < 2; kk++) {
            const int k0 = kk * 16;
            uint32_t af[4][4], bh[4][2], bl[4][2];
#pragma unroll
            for (int mi = 0; mi < 4; mi++) {
                const int r = warp_m + mi * 16 + a_row;
                ldmx4(af[mi][0], af[mi][1], af[mi][2], af[mi][3],
                      smem_u32(&cA[r * BKP + k0 + a_kh]));
            }
#pragma unroll
            for (int pr = 0; pr < 2; pr++) {
                const int r = warp_n + pr * 16 + bx4_row;
                ldmx4(bh[2 * pr][0], bh[2 * pr][1], bh[2 * pr + 1][0],
                      bh[2 * pr + 1][1], smem_u32(&cBh[r * BKP + k0 + b_kh]));
                ldmx4(bl[2 * pr][0], bl[2 * pr][1], bl[2 * pr + 1][0],
                      bl[2 * pr + 1][1], smem_u32(&cBl[r * BKP + k0 + b_kh]));
            }
#pragma unroll
            for (int mi = 0; mi < 4; mi++)
#pragma unroll
                for (int ni = 0; ni < 4; ni++) {
                    mma_f16(acc[mi][ni], af[mi], bh[ni]);
                    mma_f16(acc[mi][ni], af[mi], bl[ni]);
                }
        }
        __syncthreads();
    }

    // Epilogue by section
    const int er = brow + warp_m + (lane >> 2);
    const int ec = bcol + warp_n + (lane & 3) * 2;
#pragma unroll
    for (int mi = 0; mi < 4; mi++)
#pragma unroll
        for (int ni = 0; ni < 4; ni++) {
            const int r0 = er + mi * 16;
            const int c0 = ec + ni * 8;
            float v0 = acc[mi][ni][0] + bias[c0];
            float v1 = acc[mi][ni][1] + bias[c0 + 1];
            float v2 = acc[mi][ni][2] + bias[c0];
            float v3 = acc[mi][ni][3] + bias[c0 + 1];
            if (c0 < DM) { v0 *= 0.03125f; v1 *= 0.03125f; v2 *= 0.03125f; v3 *= 0.03125f; }
            if (c0 < 2 * DM) {
                *(uint32_t*)&g_qkvh[(size_t)r0 * QKV_N + c0] =
                    pack2h(__float2half_rn(v0), __float2half_rn(v1));
                *(uint32_t*)&g_qkvh[(size_t)(r0 + 8) * QKV_N + c0] =
                    pack2h(__float2half_rn(v2), __float2half_rn(v3));
            } else {
                uint32_t h01, l01, h23, l23;
                split2h(v0, v1, h01, l01);
                split2h(v2, v3, h23, l23);
                *(uint32_t*)&g_qkvh[(size_t)r0 * QKV_N + c0] = h01;
                *(uint32_t*)&g_qkvh[(size_t)(r0 + 8) * QKV_N + c0] = h23;
                *(uint32_t*)&g_vlo[(size_t)r0 * DM + c0 - 2 * DM] = l01;
                *(uint32_t*)&g_vlo[(size_t)(r0 + 8) * DM + c0 - 2 * DM] = l23;
            }
        }
}

// ---------------------------------------------------------------------------
// Out-proj GEMM: A 2-term fp16, B 2-term fp16, 3 MMAs (validated R7 structure).
// ---------------------------------------------------------------------------
#define O_STG (4 * TSZ)
#define OUT_DSMEM (2 * O_STG * 2)   // 81,920 B

__global__ __launch_bounds__(256) void gemm_out(
    const __half* __restrict__ Ah, const __half* __restrict__ Al,
    const __half* __restrict__ Bh, const __half* __restrict__ Bl,
    const float* __restrict__ bias, float* __restrict__ C)
{
    extern __shared__ __align__(16) __half obase[];
    const int tid  = threadIdx.x;
    const int lane = tid & 31;
    const int wid  = tid >> 5;
    const int warp_m = (wid & 1) * 64;
    const int warp_n = (wid >> 1) * 32;
    const int brow = blockIdx.y * 128;
    const int bcol = blockIdx.x * 128;

    float acc[4][4][4];
#pragma unroll
    for (int mi = 0; mi < 4; mi++)
#pragma unroll
        for (int ni = 0; ni < 4; ni++)
#pragma unroll
            for (int j = 0; j < 4; j++) acc[mi][ni][j] = 0.0f;

    const int a_row = (lane & 7) + ((lane >> 3) & 1) * 8;
    const int a_kh  = (lane >> 4) * 8;
    const int bx4_row = (lane & 7) + ((lane >> 4) & 1) * 8;
    const int b_kh  = ((lane >> 3) & 1) * 8;

#define O_ISSUE(s_, buf_)                                                        \
    do {                                                                         \
        __half* st = obase + (buf_) * O_STG;                                     \
        _Pragma("unroll") for (int u = tid; u < 512; u += 256) {                 \
            const int row = u >> 2;                                              \
            const int c8 = (u & 3) * 8;                                          \
            const size_t ga = (size_t)(brow + row) * KDIM + (s_) * 32 + c8;      \
            const size_t gb = (size_t)(bcol + row) * KDIM + (s_) * 32 + c8;      \
            cp_async16(smem_u32(st + 0 * TSZ + row * BKP + c8), &Ah[ga]);        \
            cp_async16(smem_u32(st + 1 * TSZ + row * BKP + c8), &Al[ga]);        \
            cp_async16(smem_u32(st + 2 * TSZ + row * BKP + c8), &Bh[gb]);        \
            cp_async16(smem_u32(st + 3 * TSZ + row * BKP + c8), &Bl[gb]);        \
        }                                                                        \
    } while (0)

    O_ISSUE(0, 0);
    CP_COMMIT();
    for (int s = 0; s < KDIM / 32; s++) {
        if (s + 1 < KDIM / 32) { O_ISSUE(s + 1, (s + 1) & 1); CP_COMMIT(); CP_WAIT(1); }
        else { CP_WAIT(0); }
        __syncthreads();
        const __half* cAh = obase + (s & 1) * O_STG + 0 * TSZ;
        const __half* cAl = obase + (s & 1) * O_STG + 1 * TSZ;
        const __half* cBh = obase + (s & 1) * O_STG + 2 * TSZ;
        const __half* cBl = obase + (s & 1) * O_STG + 3 * TSZ;
#pragma unroll
        for (int kk = 0; kk < 2; kk++) {
            const int k0 = kk * 16;
            uint32_t ah[4][4], al[4][4], bh[4][2], bl[4][2];
#pragma unroll
            for (int mi = 0; mi < 4; mi++) {
                const int r = warp_m + mi * 16 + a_row;
                ldmx4(ah[mi][0], ah[mi][1], ah[mi][2], ah[mi][3],
                      smem_u32(&cAh[r * BKP + k0 + a_kh]));
                ldmx4(al[mi][0], al[mi][1], al[mi][2], al[mi][3],
                      smem_u32(&cAl[r * BKP + k0 + a_kh]));
            }
#pragma unroll
            for (int pr = 0; pr < 2; pr++) {
                const int r = warp_n + pr * 16 + bx4_row;
                ldmx4(bh[2 * pr][0], bh[2 * pr][1], bh[2 * pr + 1][0],
                      bh[2 * pr + 1][1], smem_u32(&cBh[r * BKP + k0 + b_kh]));
                ldmx4(bl[2 * pr][0], bl[2 * pr][1], bl[2 * pr + 1][0],
                      bl[2 * pr + 1][1], smem_u32(&cBl[r * BKP + k0 + b_kh]));
            }
#pragma unroll
            for (int mi = 0; mi < 4; mi++)
#pragma unroll
                for (int ni = 0; ni < 4; ni++) {
                    mma_f16(acc[mi][ni], ah[mi], bh[ni]);
                    mma_f16(acc[mi][ni], ah[mi], bl[ni]);
                    mma_f16(acc[mi][ni], al[mi], bh[ni]);
                }
        }
        __syncthreads();
    }

    const int er = brow + warp_m + (lane >> 2);
    const int ec = bcol + warp_n + (lane & 3) * 2;
#pragma unroll
    for (int mi = 0; mi < 4; mi++)
#pragma unroll
        for (int ni = 0; ni < 4; ni++) {
            const int r0 = er + mi * 16;
            const int c0 = ec + ni * 8;
            float2 v0, v1;
            v0.x = acc[mi][ni][0] + bias[c0];
            v0.y = acc[mi][ni][1] + bias[c0 + 1];
            v1.x = acc[mi][ni][2] + bias[c0];
            v1.y = acc[mi][ni][3] + bias[c0 + 1];
            *(float2*)&C[(size_t)r0 * DM + c0] = v0;
            *(float2*)&C[(size_t)(r0 + 8) * DM + c0] = v1;
        }
}

// ---------------------------------------------------------------------------
// Flash attention, fp16: S = Q(single)K(single) 1 MMA; PV = P(single)V(2-term).
// cp.async double-buffered; 3 tiles/stage (K, Vh, Vl); reversed qt.
// ---------------------------------------------------------------------------
#define AT_TILE (64 * 72)
#define AT_STG (3 * AT_TILE)
#define ATTN_DSMEM (2 * AT_STG * 2)   // 55,296 B

__global__ __launch_bounds__(256) void flash_attn_f16()
{
    extern __shared__ __align__(16) __half abase[];

    const int tid = threadIdx.x, lane = tid & 31, wid = tid >> 5;
    const int qt = gridDim.x - 1 - blockIdx.x;
    const int h = blockIdx.y, b = blockIdx.z;
    const int q0 = qt * 128;
    const size_t rowb = (size_t)b * SEQ + q0;
    const int wm = wid * 16;
    const int ra = lane >> 2;
    const int kq = (lane & 3) * 2;

    // Q a-frags (single fp16) from global
    uint32_t qf[4][4];
    {
        const size_t r0 = (rowb + wm + ra) * QKV_N + h * HD;
        const size_t r1 = (rowb + wm + ra + 8) * QKV_N + h * HD;
#pragma unroll
        for (int ks = 0; ks < 4; ks++) {
            const int c = ks * 16 + kq;
            qf[ks][0] = *(const uint32_t*)&g_qkvh[r0 + c];
            qf[ks][1] = *(const uint32_t*)&g_qkvh[r1 + c];
            qf[ks][2] = *(const uint32_t*)&g_qkvh[r0 + c + 8];
            qf[ks][3] = *(const uint32_t*)&g_qkvh[r1 + c + 8];
        }
    }

    float o[8][4];
#pragma unroll
    for (int dn = 0; dn < 8; dn++)
#pragma unroll
        for (int j = 0; j < 4; j++) o[dn][j] = 0.0f;
    float m_lo = -1e30f, m_hi = -1e30f, l_lo = 0.0f, l_hi = 0.0f;

    const int bx4_row = (lane & 7) + ((lane >> 4) & 1) * 8;
    const int b_kh = ((lane >> 3) & 1) * 8;
    const int v_row = lane & 15;
    const int v_ch = ((lane >> 4) & 1) * 8;

#define KV_ISSUE(kt_, buf_)                                                        \
    do {                                                                           \
        __half* st = abase + (buf_) * AT_STG;                                      \
        const size_t gr = (size_t)b * SEQ + (kt_) * 64;                            \
        _Pragma("unroll") for (int u = tid; u < 512; u += 256) {                   \
            const int row = u >> 3;                                                \
            const int c8 = (u & 7) * 8;                                            \
            const size_t gk = (gr + row) * QKV_N + DM + h * HD + c8;               \
            const size_t gvl = (gr + row) * DM + h * HD + c8;                      \
            cp_async16(smem_u32(st + 0 * AT_TILE + row * 72 + c8), &g_qkvh[gk]);   \
            cp_async16(smem_u32(st + 1 * AT_TILE + row * 72 + c8), &g_qkvh[gk + DM]); \
            cp_async16(smem_u32(st + 2 * AT_TILE + row * 72 + c8), &g_vlo[gvl]);   \
        }                                                                          \
    } while (0)

    const int nkt = 2 * qt + 2;
    KV_ISSUE(0, 0);
    CP_COMMIT();

    for (int kt = 0; kt < nkt; kt++) {
        if (kt + 1 < nkt) { KV_ISSUE(kt + 1, (kt + 1) & 1); CP_COMMIT(); CP_WAIT(1); }
        else { CP_WAIT(0); }
        __syncthreads();
        const __half* sK  = abase + (kt & 1) * AT_STG + 0 * AT_TILE;
        const __half* sVh = abase + (kt & 1) * AT_STG + 1 * AT_TILE;
        const __half* sVl = abase + (kt & 1) * AT_STG + 2 * AT_TILE;
        const int t0 = kt * 64;

        // --- S = Q K^T (single x single) ---
        float s[8][4];
#pragma unroll
        for (int nt = 0; nt < 8; nt++)
#pragma unroll
            for (int j = 0; j < 4; j++) s[nt][j] = 0.0f;
#pragma unroll
        for (int pr = 0; pr < 4; pr++) {
            const int r = pr * 16 + bx4_row;
#pragma unroll
            for (int ks = 0; ks < 4; ks++) {
                uint32_t k0f[2], k1f[2];
                ldmx4(k0f[0], k0f[1], k1f[0], k1f[1],
                      smem_u32(&sK[r * 72 + ks * 16 + b_kh]));
                mma_f16(s[2 * pr], qf[ks], k0f);
                mma_f16(s[2 * pr + 1], qf[ks], k1f);
            }
        }

        // --- Causal mask ---
        if (t0 + 63 > q0 + wm) {
            const int row_lo = q0 + wm + ra;
            const int row_hi = row_lo + 8;
#pragma unroll
            for (int nt = 0; nt < 8; nt++) {
                const int c = t0 + nt * 8 + kq;
                if (c > row_lo) s[nt][0] = -1e30f;
                if (c + 1 > row_lo) s[nt][1] = -1e30f;
                if (c > row_hi) s[nt][2] = -1e30f;
                if (c + 1 > row_hi) s[nt][3] = -1e30f;
            }
        }

        // --- Online softmax ---
        {
            float mt0 = -1e30f, mt1 = -1e30f;
#pragma unroll
            for (int nt = 0; nt < 8; nt++) {
                mt0 = fmaxf(mt0, fmaxf(s[nt][0], s[nt][1]));
                mt1 = fmaxf(mt1, fmaxf(s[nt][2], s[nt][3]));
            }
            mt0 = fmaxf(mt0, __shfl_xor_sync(0xffffffffu, mt0, 1));
            mt0 = fmaxf(mt0, __shfl_xor_sync(0xffffffffu, mt0, 2));
            mt1 = fmaxf(mt1, __shfl_xor_sync(0xffffffffu, mt1, 1));
            mt1 = fmaxf(mt1, __shfl_xor_sync(0xffffffffu, mt1, 2));
            const float mn0 = fmaxf(m_lo, mt0);
            const float mn1 = fmaxf(m_hi, mt1);
            const float al0 = __expf(m_lo - mn0);
            const float al1 = __expf(m_hi - mn1);
            float ls0 = 0.0f, ls1 = 0.0f;
#pragma unroll
            for (int nt = 0; nt < 8; nt++) {
                s[nt][0] = __expf(s[nt][0] - mn0);
                s[nt][1] = __expf(s[nt][1] - mn0);
                s[nt][2] = __expf(s[nt][2] - mn1);
                s[nt][3] = __expf(s[nt][3] - mn1);
                ls0 += s[nt][0] + s[nt][1];
                ls1 += s[nt][2] + s[nt][3];
            }
            ls0 += __shfl_xor_sync(0xffffffffu, ls0, 1);
            ls0 += __shfl_xor_sync(0xffffffffu, ls0, 2);
            ls1 += __shfl_xor_sync(0xffffffffu, ls1, 1);
            ls1 += __shfl_xor_sync(0xffffffffu, ls1, 2);
            l_lo = l_lo * al0 + ls0;
            l_hi = l_hi * al1 + ls1;
            m_lo = mn0; m_hi = mn1;
#pragma unroll
            for (int dn = 0; dn < 8; dn++) {
                o[dn][0] *= al0; o[dn][1] *= al0;
                o[dn][2] *= al1; o[dn][3] *= al1;
            }
        }

        // --- P repack single fp16 (c-frag -> a-frag) ---
        uint32_t pf[4][4];
#pragma unroll
        for (int j = 0; j < 4; j++) {
            pf[j][0] = pack2h(__float2half_rn(s[2 * j][0]), __float2half_rn(s[2 * j][1]));
            pf[j][1] = pack2h(__float2half_rn(s[2 * j][2]), __float2half_rn(s[2 * j][3]));
            pf[j][2] = pack2h(__float2half_rn(s[2 * j + 1][0]), __float2half_rn(s[2 * j + 1][1]));
            pf[j][3] = pack2h(__float2half_rn(s[2 * j + 1][2]), __float2half_rn(s[2 * j + 1][3]));
        }

        // --- O += P V (P single x V 2-term) ---
#pragma unroll
        for (int dp = 0; dp < 4; dp++) {
#pragma unroll
            for (int j = 0; j < 4; j++) {
                uint32_t vh0[2], vh1[2], vl0[2], vl1[2];
                ldmx4t(vh0[0], vh0[1], vh1[0], vh1[1],
                       smem_u32(&sVh[(j * 16 + v_row) * 72 + dp * 16 + v_ch]));
                ldmx4t(vl0[0], vl0[1], vl1[0], vl1[1],
                       smem_u32(&sVl[(j * 16 + v_row) * 72 + dp * 16 + v_ch]));
                mma_f16(o[2 * dp], pf[j], vh0);
                mma_f16(o[2 * dp], pf[j], vl0);
                mma_f16(o[2 * dp + 1], pf[j], vh1);
                mma_f16(o[2 * dp + 1], pf[j], vl1);
            }
        }
        __syncthreads();
    }

    // --- Finalize: 2-term fp16 for the out-proj A operand ---
    const float il = 1.0f / l_lo;
    const float ih = 1.0f / l_hi;
    const size_t row_lo_g = rowb + wm + ra;
    const size_t row_hi_g = row_lo_g + 8;
#pragma unroll
    for (int dn = 0; dn < 8; dn++) {
        const int col = h * HD + dn * 8 + kq;
        uint32_t h01, l01, h23, l23;
        split2h(o[dn][0] * il, o[dn][1] * il, h01, l01);
        split2h(o[dn][2] * ih, o[dn][3] * ih, h23, l23);
        *(uint32_t*)&g_ath[row_lo_g * DM + col] = h01;
        *(uint32_t*)&g_atl[row_lo_g * DM + col] = l01;
        *(uint32_t*)&g_ath[row_hi_g * DM + col] = h23;
        *(uint32_t*)&g_atl[row_hi_g * DM + col] = l23;
    }
}

// ---------------------------------------------------------------------------
// Launcher
// ---------------------------------------------------------------------------
extern "C" void kernel_launch(void* const* d_in, const int* in_sizes, int n_in,
                              void* d_out, int out_size)
{
    const float* x     = (const float*)d_in[0];
    const float* w_qkv = (const float*)d_in[1];
    const float* b_qkv = (const float*)d_in[2];
    const float* w_out = (const float*)d_in[3];
    const float* b_out = (const float*)d_in[4];
    float* out = (float*)d_out;

    __half *xh, *wqh, *wql, *woh, *wol, *ath, *atl;
    cudaGetSymbolAddress((void**)&xh, g_xh);
    cudaGetSymbolAddress((void**)&wqh, g_wqh);
    cudaGetSymbolAddress((void**)&wql, g_wql);
    cudaGetSymbolAddress((void**)&woh, g_woh);
    cudaGetSymbolAddress((void**)&wol, g_wol);
    cudaGetSymbolAddress((void**)&ath, g_ath);
    cudaGetSymbolAddress((void**)&atl, g_atl);

    cudaFuncSetAttribute(gemm_qkv, cudaFuncAttributeMaxDynamicSharedMemorySize, QKV_DSMEM);
    cudaFuncSetAttribute(gemm_out, cudaFuncAttributeMaxDynamicSharedMemorySize, OUT_DSMEM);
    cudaFuncSetAttribute(flash_attn_f16, cudaFuncAttributeMaxDynamicSharedMemorySize, ATTN_DSMEM);

    // Preprocessing
    to_f16<<<(MROWS * KDIM / 4 + 255) / 256, 256>>>(x, xh, MROWS * KDIM);
    transpose_split<<<dim3(QKV_N / 32, KDIM / 32), dim3(32, 8)>>>(w_qkv, wqh, wql, KDIM, QKV_N);
    transpose_split<<<dim3(DM / 32, KDIM / 32), dim3(32, 8)>>>(w_out, woh, wol, KDIM, DM);

    // 1) QKV projection (2-MMA fp16) -> g_qkvh (+ g_vlo)
    gemm_qkv<<<dim3(QKV_N / 128, MROWS / 128), 256, QKV_DSMEM>>>(
        xh, wqh, wql, b_qkv);

    // 2) Attention (1-MMA S, 2-MMA PV) -> g_ath/g_atl
    flash_attn_f16<<<dim3(SEQ / 128, NH, BSZ), 256, ATTN_DSMEM>>>();

    // 3) Out projection (3-MMA fp16) -> fp32 output
    gemm_out<<<dim3(DM / 128, MROWS / 128), 256, OUT_DSMEM>>>(
        ath, atl, woh, wol, b_out, out);
}

// round 11
// speedup vs baseline: 5.7001x; 1.4408x over previous
#include <cuda_runtime.h>
#include <cuda_fp16.h>
#include <cstdint>

// Problem constants
#define BSZ 2
#define SEQ 2048
#define DM 1024
#define NH 16
#define HD 64
#define MROWS 4096
#define QKV_N 3072
#define KDIM 1024

// ---------------------------------------------------------------------------
// Scratch (__device__ globals; allocation-free rule)
// ---------------------------------------------------------------------------
__device__ __align__(16) __half g_xh[MROWS * KDIM];        // x single fp16
__device__ __align__(16) __half g_wqh[QKV_N * KDIM];       // w_qkv^T single
__device__ __align__(16) __half g_woh[DM * KDIM];          // w_out^T hi
__device__ __align__(16) __half g_wol[DM * KDIM];          // w_out^T lo
__device__ __align__(16) __half g_qkvh[MROWS * QKV_N];     // Q(scaled) K V, all single
__device__ __align__(16) __half g_ath[MROWS * DM];         // attn out single

// ---------------------------------------------------------------------------
// PTX helpers
// ---------------------------------------------------------------------------
__device__ __forceinline__ uint32_t smem_u32(const void* p) {
    uint32_t a;
    asm("{ .reg .u64 t; cvta.to.shared.u64 t, %1; cvt.u32.u64 %0, t; }" : "=r"(a) : "l"(p));
    return a;
}
__device__ __forceinline__ void ldmx4(uint32_t& r0, uint32_t& r1, uint32_t& r2,
                                      uint32_t& r3, uint32_t addr) {
    asm volatile("ldmatrix.sync.aligned.m8n8.x4.shared.b16 {%0,%1,%2,%3}, [%4];"
                 : "=r"(r0), "=r"(r1), "=r"(r2), "=r"(r3) : "r"(addr));
}
__device__ __forceinline__ void ldmx4t(uint32_t& r0, uint32_t& r1, uint32_t& r2,
                                       uint32_t& r3, uint32_t addr) {
    asm volatile("ldmatrix.sync.aligned.m8n8.x4.trans.shared.b16 {%0,%1,%2,%3}, [%4];"
                 : "=r"(r0), "=r"(r1), "=r"(r2), "=r"(r3) : "r"(addr));
}
__device__ __forceinline__ void mma_f16(float* c, const uint32_t* a, const uint32_t* b) {
    asm volatile(
        "mma.sync.aligned.m16n8k16.row.col.f32.f16.f16.f32 "
        "{%0,%1,%2,%3}, {%4,%5,%6,%7}, {%8,%9}, {%0,%1,%2,%3};"
        : "+f"(c[0]), "+f"(c[1]), "+f"(c[2]), "+f"(c[3])
        : "r"(a[0]), "r"(a[1]), "r"(a[2]), "r"(a[3]), "r"(b[0]), "r"(b[1]));
}
__device__ __forceinline__ void cp_async16(uint32_t saddr, const void* g) {
    asm volatile("cp.async.cg.shared.global [%0], [%1], 16;" :: "r"(saddr), "l"(g));
}
#define CP_COMMIT() asm volatile("cp.async.commit_group;" ::: "memory")
#define CP_WAIT(n)  asm volatile("cp.async.wait_group %0;" :: "n"(n) : "memory")

__device__ __forceinline__ uint32_t pack2h(__half a, __half b) {
    __half2 t = __halves2half2(a, b);
    return *reinterpret_cast<uint32_t*>(&t);
}
__device__ __forceinline__ void split2h(float a, float b, uint32_t& hi, uint32_t& lo) {
    __half ha = __float2half_rn(a), hb = __float2half_rn(b);
    hi = pack2h(ha, hb);
    lo = pack2h(__float2half_rn(a - __half2float(ha)),
                __float2half_rn(b - __half2float(hb)));
}

// ---------------------------------------------------------------------------
// Preprocessing
// ---------------------------------------------------------------------------
__global__ __launch_bounds__(256) void to_f16(
    const float* __restrict__ src, __half* __restrict__ dst, int n)
{
    int i = (blockIdx.x * 256 + threadIdx.x) * 4;
    if (i >= n) return;
    float4 v = *(const float4*)&src[i];
    uint2 o;
    o.x = pack2h(__float2half_rn(v.x), __float2half_rn(v.y));
    o.y = pack2h(__float2half_rn(v.z), __float2half_rn(v.w));
    *(uint2*)&dst[i] = o;
}

// w [K,N] fp32 -> single fp16 transposed [N,K]
__global__ __launch_bounds__(256) void transpose_h(
    const float* __restrict__ w, __half* __restrict__ th, int K, int N)
{
    __shared__ float tile[32][33];
    const int nx = blockIdx.x * 32 + threadIdx.x;
    const int k0 = blockIdx.y * 32;
#pragma unroll
    for (int j = 0; j < 32; j += 8)
        tile[threadIdx.y + j][threadIdx.x] = w[(size_t)(k0 + threadIdx.y + j) * N + nx];
    __syncthreads();
    const int kx = k0 + threadIdx.x;
    const int n0 = blockIdx.x * 32;
#pragma unroll
    for (int j = 0; j < 32; j += 8)
        th[(size_t)(n0 + threadIdx.y + j) * K + kx] =
            __float2half_rn(tile[threadIdx.x][threadIdx.y + j]);
}

// w [K,N] fp32 -> 2-term fp16 transposed [N,K]
__global__ __launch_bounds__(256) void transpose_split(
    const float* __restrict__ w, __half* __restrict__ th,
    __half* __restrict__ tl, int K, int N)
{
    __shared__ float tile[32][33];
    const int nx = blockIdx.x * 32 + threadIdx.x;
    const int k0 = blockIdx.y * 32;
#pragma unroll
    for (int j = 0; j < 32; j += 8)
        tile[threadIdx.y + j][threadIdx.x] = w[(size_t)(k0 + threadIdx.y + j) * N + nx];
    __syncthreads();
    const int kx = k0 + threadIdx.x;
    const int n0 = blockIdx.x * 32;
#pragma unroll
    for (int j = 0; j < 32; j += 8) {
        float v = tile[threadIdx.x][threadIdx.y + j];
        __half hh = __float2half_rn(v);
        th[(size_t)(n0 + threadIdx.y + j) * K + kx] = hh;
        tl[(size_t)(n0 + threadIdx.y + j) * K + kx] = __float2half_rn(v - __half2float(hh));
    }
}

// ---------------------------------------------------------------------------
// QKV GEMM: A single x B single, 1 MMA. 128x128 CTA, BK=32, 8 warps,
// 2-stage cp.async (2 tiles/stage). Epilogue: Q scaled 1/32, all single fp16.
// ---------------------------------------------------------------------------
#define BKP 40
#define TSZ (128 * BKP)
#define Q_STG (2 * TSZ)
#define QKV_DSMEM (2 * Q_STG * 2)   // 40,960 B

__global__ __launch_bounds__(256) void gemm_qkv(
    const __half* __restrict__ A, const __half* __restrict__ B,
    const float* __restrict__ bias)
{
    extern __shared__ __align__(16) __half qbase[];
    const int tid  = threadIdx.x;
    const int lane = tid & 31;
    const int wid  = tid >> 5;
    const int warp_m = (wid & 1) * 64;
    const int warp_n = (wid >> 1) * 32;
    const int brow = blockIdx.y * 128;
    const int bcol = blockIdx.x * 128;

    float acc[4][4][4];
#pragma unroll
    for (int mi = 0; mi < 4; mi++)
#pragma unroll
        for (int ni = 0; ni < 4; ni++)
#pragma unroll
            for (int j = 0; j < 4; j++) acc[mi][ni][j] = 0.0f;

    const int a_row = (lane & 7) + ((lane >> 3) & 1) * 8;
    const int a_kh  = (lane >> 4) * 8;
    const int bx4_row = (lane & 7) + ((lane >> 4) & 1) * 8;
    const int b_kh  = ((lane >> 3) & 1) * 8;

#define Q_ISSUE(s_, buf_)                                                        \
    do {                                                                         \
        __half* st = qbase + (buf_) * Q_STG;                                     \
        _Pragma("unroll") for (int u = tid; u < 512; u += 256) {                 \
            const int row = u >> 2;                                              \
            const int c8 = (u & 3) * 8;                                          \
            const size_t ga = (size_t)(brow + row) * KDIM + (s_) * 32 + c8;      \
            const size_t gb = (size_t)(bcol + row) * KDIM + (s_) * 32 + c8;      \
            cp_async16(smem_u32(st + 0 * TSZ + row * BKP + c8), &A[ga]);         \
            cp_async16(smem_u32(st + 1 * TSZ + row * BKP + c8), &B[gb]);         \
        }                                                                        \
    } while (0)

    Q_ISSUE(0, 0);
    CP_COMMIT();
    for (int s = 0; s < KDIM / 32; s++) {
        if (s + 1 < KDIM / 32) { Q_ISSUE(s + 1, (s + 1) & 1); CP_COMMIT(); CP_WAIT(1); }
        else { CP_WAIT(0); }
        __syncthreads();
        const __half* cA = qbase + (s & 1) * Q_STG + 0 * TSZ;
        const __half* cB = qbase + (s & 1) * Q_STG + 1 * TSZ;
#pragma unroll
        for (int kk = 0; kk < 2; kk++) {
            const int k0 = kk * 16;
            uint32_t af[4][4], bf[4][2];
#pragma unroll
            for (int mi = 0; mi < 4; mi++) {
                const int r = warp_m + mi * 16 + a_row;
                ldmx4(af[mi][0], af[mi][1], af[mi][2], af[mi][3],
                      smem_u32(&cA[r * BKP + k0 + a_kh]));
            }
#pragma unroll
            for (int pr = 0; pr < 2; pr++) {
                const int r = warp_n + pr * 16 + bx4_row;
                ldmx4(bf[2 * pr][0], bf[2 * pr][1], bf[2 * pr + 1][0],
                      bf[2 * pr + 1][1], smem_u32(&cB[r * BKP + k0 + b_kh]));
            }
#pragma unroll
            for (int mi = 0; mi < 4; mi++)
#pragma unroll
                for (int ni = 0; ni < 4; ni++)
                    mma_f16(acc[mi][ni], af[mi], bf[ni]);
        }
        __syncthreads();
    }

    const int er = brow + warp_m + (lane >> 2);
    const int ec = bcol + warp_n + (lane & 3) * 2;
#pragma unroll
    for (int mi = 0; mi < 4; mi++)
#pragma unroll
        for (int ni = 0; ni < 4; ni++) {
            const int r0 = er + mi * 16;
            const int c0 = ec + ni * 8;
            float v0 = acc[mi][ni][0] + bias[c0];
            float v1 = acc[mi][ni][1] + bias[c0 + 1];
            float v2 = acc[mi][ni][2] + bias[c0];
            float v3 = acc[mi][ni][3] + bias[c0 + 1];
            if (c0 < DM) { v0 *= 0.03125f; v1 *= 0.03125f; v2 *= 0.03125f; v3 *= 0.03125f; }
            *(uint32_t*)&g_qkvh[(size_t)r0 * QKV_N + c0] =
                pack2h(__float2half_rn(v0), __float2half_rn(v1));
            *(uint32_t*)&g_qkvh[(size_t)(r0 + 8) * QKV_N + c0] =
                pack2h(__float2half_rn(v2), __float2half_rn(v3));
        }
}

// ---------------------------------------------------------------------------
// Out-proj GEMM: A single x B 2-term, 2 MMAs. 3 tiles/stage.
// ---------------------------------------------------------------------------
#define O_STG (3 * TSZ)
#define OUT_DSMEM (2 * O_STG * 2)   // 61,440 B

__global__ __launch_bounds__(256) void gemm_out(
    const __half* __restrict__ A, const __half* __restrict__ Bh,
    const __half* __restrict__ Bl, const float* __restrict__ bias,
    float* __restrict__ C)
{
    extern __shared__ __align__(16) __half obase[];
    const int tid  = threadIdx.x;
    const int lane = tid & 31;
    const int wid  = tid >> 5;
    const int warp_m = (wid & 1) * 64;
    const int warp_n = (wid >> 1) * 32;
    const int brow = blockIdx.y * 128;
    const int bcol = blockIdx.x * 128;

    float acc[4][4][4];
#pragma unroll
    for (int mi = 0; mi < 4; mi++)
#pragma unroll
        for (int ni = 0; ni < 4; ni++)
#pragma unroll
            for (int j = 0; j < 4; j++) acc[mi][ni][j] = 0.0f;

    const int a_row = (lane & 7) + ((lane >> 3) & 1) * 8;
    const int a_kh  = (lane >> 4) * 8;
    const int bx4_row = (lane & 7) + ((lane >> 4) & 1) * 8;
    const int b_kh  = ((lane >> 3) & 1) * 8;

#define O_ISSUE(s_, buf_)                                                        \
    do {                                                                         \
        __half* st = obase + (buf_) * O_STG;                                     \
        _Pragma("unroll") for (int u = tid; u < 512; u += 256) {                 \
            const int row = u >> 2;                                              \
            const int c8 = (u & 3) * 8;                                          \
            const size_t ga = (size_t)(brow + row) * KDIM + (s_) * 32 + c8;      \
            const size_t gb = (size_t)(bcol + row) * KDIM + (s_) * 32 + c8;      \
            cp_async16(smem_u32(st + 0 * TSZ + row * BKP + c8), &A[ga]);         \
            cp_async16(smem_u32(st + 1 * TSZ + row * BKP + c8), &Bh[gb]);        \
            cp_async16(smem_u32(st + 2 * TSZ + row * BKP + c8), &Bl[gb]);        \
        }                                                                        \
    } while (0)

    O_ISSUE(0, 0);
    CP_COMMIT();
    for (int s = 0; s < KDIM / 32; s++) {
        if (s + 1 < KDIM / 32) { O_ISSUE(s + 1, (s + 1) & 1); CP_COMMIT(); CP_WAIT(1); }
        else { CP_WAIT(0); }
        __syncthreads();
        const __half* cA  = obase + (s & 1) * O_STG + 0 * TSZ;
        const __half* cBh = obase + (s & 1) * O_STG + 1 * TSZ;
        const __half* cBl = obase + (s & 1) * O_STG + 2 * TSZ;
#pragma unroll
        for (int kk = 0; kk < 2; kk++) {
            const int k0 = kk * 16;
            uint32_t af[4][4], bh[4][2], bl[4][2];
#pragma unroll
            for (int mi = 0; mi < 4; mi++) {
                const int r = warp_m + mi * 16 + a_row;
                ldmx4(af[mi][0], af[mi][1], af[mi][2], af[mi][3],
                      smem_u32(&cA[r * BKP + k0 + a_kh]));
            }
#pragma unroll
            for (int pr = 0; pr < 2; pr++) {
                const int r = warp_n + pr * 16 + bx4_row;
                ldmx4(bh[2 * pr][0], bh[2 * pr][1], bh[2 * pr + 1][0],
                      bh[2 * pr + 1][1], smem_u32(&cBh[r * BKP + k0 + b_kh]));
                ldmx4(bl[2 * pr][0], bl[2 * pr][1], bl[2 * pr + 1][0],
                      bl[2 * pr + 1][1], smem_u32(&cBl[r * BKP + k0 + b_kh]));
            }
#pragma unroll
            for (int mi = 0; mi < 4; mi++)
#pragma unroll
                for (int ni = 0; ni < 4; ni++) {
                    mma_f16(acc[mi][ni], af[mi], bh[ni]);
                    mma_f16(acc[mi][ni], af[mi], bl[ni]);
                }
        }
        __syncthreads();
    }

    const int er = brow + warp_m + (lane >> 2);
    const int ec = bcol + warp_n + (lane & 3) * 2;
#pragma unroll
    for (int mi = 0; mi < 4; mi++)
#pragma unroll
        for (int ni = 0; ni < 4; ni++) {
            const int r0 = er + mi * 16;
            const int c0 = ec + ni * 8;
            float2 v0, v1;
            v0.x = acc[mi][ni][0] + bias[c0];
            v0.y = acc[mi][ni][1] + bias[c0 + 1];
            v1.x = acc[mi][ni][2] + bias[c0];
            v1.y = acc[mi][ni][3] + bias[c0 + 1];
            *(float2*)&C[(size_t)r0 * DM + c0] = v0;
            *(float2*)&C[(size_t)(r0 + 8) * DM + c0] = v1;
        }
}

// ---------------------------------------------------------------------------
// Flash attention fp16: S = QK (1 MMA), PV = P x V (1 MMA).
// cp.async double-buffered, 2 tiles/stage (K, V); reversed qt.
// ---------------------------------------------------------------------------
#define AT_TILE (64 * 72)
#define AT_STG (2 * AT_TILE)
#define ATTN_DSMEM (2 * AT_STG * 2)   // 36,864 B

__global__ __launch_bounds__(256) void flash_attn_f16()
{
    extern __shared__ __align__(16) __half abase[];

    const int tid = threadIdx.x, lane = tid & 31, wid = tid >> 5;
    const int qt = gridDim.x - 1 - blockIdx.x;
    const int h = blockIdx.y, b = blockIdx.z;
    const int q0 = qt * 128;
    const size_t rowb = (size_t)b * SEQ + q0;
    const int wm = wid * 16;
    const int ra = lane >> 2;
    const int kq = (lane & 3) * 2;

    // Q a-frags (single fp16) from global
    uint32_t qf[4][4];
    {
        const size_t r0 = (rowb + wm + ra) * QKV_N + h * HD;
        const size_t r1 = (rowb + wm + ra + 8) * QKV_N + h * HD;
#pragma unroll
        for (int ks = 0; ks < 4; ks++) {
            const int c = ks * 16 + kq;
            qf[ks][0] = *(const uint32_t*)&g_qkvh[r0 + c];
            qf[ks][1] = *(const uint32_t*)&g_qkvh[r1 + c];
            qf[ks][2] = *(const uint32_t*)&g_qkvh[r0 + c + 8];
            qf[ks][3] = *(const uint32_t*)&g_qkvh[r1 + c + 8];
        }
    }

    float o[8][4];
#pragma unroll
    for (int dn = 0; dn < 8; dn++)
#pragma unroll
        for (int j = 0; j < 4; j++) o[dn][j] = 0.0f;
    float m_lo = -1e30f, m_hi = -1e30f, l_lo = 0.0f, l_hi = 0.0f;

    const int bx4_row = (lane & 7) + ((lane >> 4) & 1) * 8;
    const int b_kh = ((lane >> 3) & 1) * 8;
    const int v_row = lane & 15;
    const int v_ch = ((lane >> 4) & 1) * 8;

#define KV_ISSUE(kt_, buf_)                                                        \
    do {                                                                           \
        __half* st = abase + (buf_) * AT_STG;                                      \
        const size_t gr = (size_t)b * SEQ + (kt_) * 64;                            \
        _Pragma("unroll") for (int u = tid; u < 512; u += 256) {                   \
            const int row = u >> 3;                                                \
            const int c8 = (u & 7) * 8;                                            \
            const size_t gk = (gr + row) * QKV_N + DM + h * HD + c8;               \
            cp_async16(smem_u32(st + 0 * AT_TILE + row * 72 + c8), &g_qkvh[gk]);   \
            cp_async16(smem_u32(st + 1 * AT_TILE + row * 72 + c8), &g_qkvh[gk + DM]); \
        }                                                                          \
    } while (0)

    const int nkt = 2 * qt + 2;
    KV_ISSUE(0, 0);
    CP_COMMIT();

    for (int kt = 0; kt < nkt; kt++) {
        if (kt + 1 < nkt) { KV_ISSUE(kt + 1, (kt + 1) & 1); CP_COMMIT(); CP_WAIT(1); }
        else { CP_WAIT(0); }
        __syncthreads();
        const __half* sK = abase + (kt & 1) * AT_STG + 0 * AT_TILE;
        const __half* sV = abase + (kt & 1) * AT_STG + 1 * AT_TILE;
        const int t0 = kt * 64;

        // --- S = Q K^T ---
        float s[8][4];
#pragma unroll
        for (int nt = 0; nt < 8; nt++)
#pragma unroll
            for (int j = 0; j < 4; j++) s[nt][j] = 0.0f;
#pragma unroll
        for (int pr = 0; pr < 4; pr++) {
            const int r = pr * 16 + bx4_row;
#pragma unroll
            for (int ks = 0; ks < 4; ks++) {
                uint32_t k0f[2], k1f[2];
                ldmx4(k0f[0], k0f[1], k1f[0], k1f[1],
                      smem_u32(&sK[r * 72 + ks * 16 + b_kh]));
                mma_f16(s[2 * pr], qf[ks], k0f);
                mma_f16(s[2 * pr + 1], qf[ks], k1f);
            }
        }

        // --- Causal mask ---
        if (t0 + 63 > q0 + wm) {
            const int row_lo = q0 + wm + ra;
            const int row_hi = row_lo + 8;
#pragma unroll
            for (int nt = 0; nt < 8; nt++) {
                const int c = t0 + nt * 8 + kq;
                if (c > row_lo) s[nt][0] = -1e30f;
                if (c + 1 > row_lo) s[nt][1] = -1e30f;
                if (c > row_hi) s[nt][2] = -1e30f;
                if (c + 1 > row_hi) s[nt][3] = -1e30f;
            }
        }

        // --- Online softmax ---
        {
            float mt0 = -1e30f, mt1 = -1e30f;
#pragma unroll
            for (int nt = 0; nt < 8; nt++) {
                mt0 = fmaxf(mt0, fmaxf(s[nt][0], s[nt][1]));
                mt1 = fmaxf(mt1, fmaxf(s[nt][2], s[nt][3]));
            }
            mt0 = fmaxf(mt0, __shfl_xor_sync(0xffffffffu, mt0, 1));
            mt0 = fmaxf(mt0, __shfl_xor_sync(0xffffffffu, mt0, 2));
            mt1 = fmaxf(mt1, __shfl_xor_sync(0xffffffffu, mt1, 1));
            mt1 = fmaxf(mt1, __shfl_xor_sync(0xffffffffu, mt1, 2));
            const float mn0 = fmaxf(m_lo, mt0);
            const float mn1 = fmaxf(m_hi, mt1);
            const float al0 = __expf(m_lo - mn0);
            const float al1 = __expf(m_hi - mn1);
            float ls0 = 0.0f, ls1 = 0.0f;
#pragma unroll
            for (int nt = 0; nt < 8; nt++) {
                s[nt][0] = __expf(s[nt][0] - mn0);
                s[nt][1] = __expf(s[nt][1] - mn0);
                s[nt][2] = __expf(s[nt][2] - mn1);
                s[nt][3] = __expf(s[nt][3] - mn1);
                ls0 += s[nt][0] + s[nt][1];
                ls1 += s[nt][2] + s[nt][3];
            }
            ls0 += __shfl_xor_sync(0xffffffffu, ls0, 1);
            ls0 += __shfl_xor_sync(0xffffffffu, ls0, 2);
            ls1 += __shfl_xor_sync(0xffffffffu, ls1, 1);
            ls1 += __shfl_xor_sync(0xffffffffu, ls1, 2);
            l_lo = l_lo * al0 + ls0;
            l_hi = l_hi * al1 + ls1;
            m_lo = mn0; m_hi = mn1;
#pragma unroll
            for (int dn = 0; dn < 8; dn++) {
                o[dn][0] *= al0; o[dn][1] *= al0;
                o[dn][2] *= al1; o[dn][3] *= al1;
            }
        }

        // --- P repack single fp16 (c-frag -> a-frag) ---
        uint32_t pf[4][4];
#pragma unroll
        for (int j = 0; j < 4; j++) {
            pf[j][0] = pack2h(__float2half_rn(s[2 * j][0]), __float2half_rn(s[2 * j][1]));
            pf[j][1] = pack2h(__float2half_rn(s[2 * j][2]), __float2half_rn(s[2 * j][3]));
            pf[j][2] = pack2h(__float2half_rn(s[2 * j + 1][0]), __float2half_rn(s[2 * j + 1][1]));
            pf[j][3] = pack2h(__float2half_rn(s[2 * j + 1][2]), __float2half_rn(s[2 * j + 1][3]));
        }

        // --- O += P V (single x single) ---
#pragma unroll
        for (int dp = 0; dp < 4; dp++) {
#pragma unroll
            for (int j = 0; j < 4; j++) {
                uint32_t v0f[2], v1f[2];
                ldmx4t(v0f[0], v0f[1], v1f[0], v1f[1],
                       smem_u32(&sV[(j * 16 + v_row) * 72 + dp * 16 + v_ch]));
                mma_f16(o[2 * dp], pf[j], v0f);
                mma_f16(o[2 * dp + 1], pf[j], v1f);
            }
        }
        __syncthreads();
    }

    // --- Finalize: single fp16 store for the out-proj A operand ---
    const float il = 1.0f / l_lo;
    const float ih = 1.0f / l_hi;
    const size_t row_lo_g = rowb + wm + ra;
    const size_t row_hi_g = row_lo_g + 8;
#pragma unroll
    for (int dn = 0; dn < 8; dn++) {
        const int col = h * HD + dn * 8 + kq;
        *(uint32_t*)&g_ath[row_lo_g * DM + col] =
            pack2h(__float2half_rn(o[dn][0] * il), __float2half_rn(o[dn][1] * il));
        *(uint32_t*)&g_ath[row_hi_g * DM + col] =
            pack2h(__float2half_rn(o[dn][2] * ih), __float2half_rn(o[dn][3] * ih));
    }
}

// ---------------------------------------------------------------------------
// Launcher
// ---------------------------------------------------------------------------
extern "C" void kernel_launch(void* const* d_in, const int* in_sizes, int n_in,
                              void* d_out, int out_size)
{
    const float* x     = (const float*)d_in[0];
    const float* w_qkv = (const float*)d_in[1];
    const float* b_qkv = (const float*)d_in[2];
    const float* w_out = (const float*)d_in[3];
    const float* b_out = (const float*)d_in[4];
    float* out = (float*)d_out;

    __half *xh, *wqh, *woh, *wol, *ath;
    cudaGetSymbolAddress((void**)&xh, g_xh);
    cudaGetSymbolAddress((void**)&wqh, g_wqh);
    cudaGetSymbolAddress((void**)&woh, g_woh);
    cudaGetSymbolAddress((void**)&wol, g_wol);
    cudaGetSymbolAddress((void**)&ath, g_ath);

    cudaFuncSetAttribute(gemm_qkv, cudaFuncAttributeMaxDynamicSharedMemorySize, QKV_DSMEM);
    cudaFuncSetAttribute(gemm_out, cudaFuncAttributeMaxDynamicSharedMemorySize, OUT_DSMEM);
    cudaFuncSetAttribute(flash_attn_f16, cudaFuncAttributeMaxDynamicSharedMemorySize, ATTN_DSMEM);

    // Preprocessing
    to_f16<<<(MROWS * KDIM / 4 + 255) / 256, 256>>>(x, xh, MROWS * KDIM);
    transpose_h<<<dim3(QKV_N / 32, KDIM / 32), dim3(32, 8)>>>(w_qkv, wqh, KDIM, QKV_N);
    transpose_split<<<dim3(DM / 32, KDIM / 32), dim3(32, 8)>>>(w_out, woh, wol, KDIM, DM);

    // 1) QKV projection (1-MMA fp16) -> g_qkvh
    gemm_qkv<<<dim3(QKV_N / 128, MROWS / 128), 256, QKV_DSMEM>>>(xh, wqh, b_qkv);

    // 2) Attention (1-MMA S, 1-MMA PV) -> g_ath
    flash_attn_f16<<<dim3(SEQ / 128, NH, BSZ), 256, ATTN_DSMEM>>>();

    // 3) Out projection (2-MMA fp16) -> fp32 output
    gemm_out<<<dim3(DM / 128, MROWS / 128), 256, OUT_DSMEM>>>(
        ath, woh, wol, b_out, out);
}